// round 14
// baseline (speedup 1.0000x reference)
#include <cuda_runtime.h>
#include <cstdint>
#include <cstddef>

#define NPT 262144
#define C0  262144
#define NBLK 148
#define NTHR 1024
#define GSTRIDE (NBLK * NTHR)
#define FULLM 0xffffffffu
#define SMSZ 34176
#define SMBM 33280
typedef unsigned long long ull;

__constant__ int cNX[27] = {-1,0,1,-1,0,1,-1,0,1,-1,0,1,-1,0,1,-1,0,1,-1,0,1,-1,0,1,-1,0,1};
__constant__ int cNY[27] = {-1,-1,-1,0,0,0,1,1,1,-1,-1,-1,0,0,0,1,1,1,-1,-1,-1,0,0,0,1,1,1};
__constant__ int cNZ[27] = {-1,-1,-1,-1,-1,-1,-1,-1,-1,0,0,0,0,0,0,0,0,0,1,1,1,1,1,1,1,1,1};

struct __align__(256) GG {
    // ---------- zero block (memset each launch) ----------
    int   cnt0[C0];
    int   cur0[C0];
    int   cntLcell[32768];
    int   curL[32768];
    int   tick[16];
    ull   scanflags[2304];
    int   tot[16];          // 0..4 = n_l, 5 = T, 6 = E
    int   mnb[4], mxb[4];   // mnb stores (0x7fffffff - bits) under atomicMax
    int   barcnt;
    int   pad0[3];
    int   zend[4];
    // ---------- rest ----------
    int   cid[NPT];
    int   rank0[C0];
    int   cstart0[C0];
    int   order0[NPT];
    int   seg0[NPT];
    int   pdeg[NPT];
    int   poff[NPT];
    int   neA[299584];
    int   rankL[32768];
    int   cstartLcell[32768];
    int   segL[299520];
    int   ordL[299520];
    int   cntR[37440];
    int   cstR[37440];
    int   bmask[216];
    int   Stab[3 * 128 * 6];
    int   Ttab[3 * 128 * 6];
    float bnd[3 * 63];
    int   pad1[32];
    int oassign, osv, oedge, oids, A, S, E;
    int svb[5], ab[5];
};
__device__ GG g;

__device__ __align__(128) int g_rinfo0[C0];
__device__ __align__(128) int g_rinfoL[37440];
__device__ __align__(128) int g_ecnt8[1011200];
__device__ __align__(128) int g_eoff8[1011200];
__device__ float g_svraw[299584 * 10];

__device__ __forceinline__ int ldv(const int* p) { return *(const volatile int*)p; }

__device__ __forceinline__ int wscan(int x) {
    int lane = threadIdx.x & 31;
#pragma unroll
    for (int d = 1; d < 32; d <<= 1) {
        int y = __shfl_up_sync(FULLM, x, d);
        if (lane >= d) x += y;
    }
    return x;
}
__device__ __forceinline__ ull wscan64(ull x) {
    int lane = threadIdx.x & 31;
#pragma unroll
    for (int d = 1; d < 32; d <<= 1) {
        ull y = __shfl_up_sync(FULLM, x, d);
        if (lane >= d) x += y;
    }
    return x;
}

// ------------------------------------------------------------------ scan device funcs (virtual tiles)
__device__ void scan1_dev(const int* __restrict__ in, int* __restrict__ out,
                          int n, int* tot, int ti, int fo, char* sm) {
    int tid = threadIdx.x;
    int* sbid = (int*)sm;
    int* sexc = (int*)sm + 1;
    int* wsum = (int*)sm + 8;
    int* woff = (int*)sm + 48;
    int nb = (n + 8191) / 8192;
    while (true) {
        __syncthreads();
        if (tid == 0) *sbid = atomicAdd(&g.tick[ti], 1);
        __syncthreads();
        int bid = *sbid;
        if (bid >= nb) break;
        int base = bid * 8192 + tid * 8;
        int v[8]; int t = 0;
#pragma unroll
        for (int j = 0; j < 8; j++) { v[j] = (base + j < n) ? __ldcg(in + base + j) : 0; t += v[j]; }
        int inc = wscan(t);
        if ((tid & 31) == 31) wsum[tid >> 5] = inc;
        __syncthreads();
        if (tid < 32) {
            int x = wsum[tid];
            int iw = wscan(x);
            woff[tid] = iw - x;
            int B = __shfl_sync(FULLM, iw, 31);
            ull* fl = g.scanflags + fo;
            int exc = 0;
            if (bid == 0) {
                if (tid == 0) atomicExch(&fl[0], (2ULL << 62) | (unsigned)B);
            } else {
                if (tid == 0) atomicExch(&fl[bid], (1ULL << 62) | (unsigned)B);
                int lb = bid - 1;
                while (true) {
                    int idx = lb - tid;
                    ull w = 0; int st = 2;
                    if (idx >= 0) {
                        do { w = atomicAdd(&fl[idx], 0ULL); } while (!(w >> 62));
                        st = (int)(w >> 62);
                    }
                    unsigned pm = __ballot_sync(FULLM, st == 2);
                    int val = (int)(unsigned)w;
                    int firstP = pm ? (__ffs(pm) - 1) : 32;
                    if (tid > firstP) val = 0;
#pragma unroll
                    for (int d = 16; d >= 1; d >>= 1) val += __shfl_xor_sync(FULLM, val, d);
                    exc += val;
                    if (pm) break;
                    lb -= 32;
                }
                if (tid == 0) atomicExch(&fl[bid], (2ULL << 62) | (unsigned)(exc + B));
            }
            if (tid == 0) { *sexc = exc; if (tot && bid == nb - 1) *tot = exc + B; }
        }
        __syncthreads();
        int off = *sexc + woff[tid >> 5] + inc - t;
#pragma unroll
        for (int j = 0; j < 8; j++) { if (base + j < n) out[base + j] = off; off += v[j]; }
    }
}

#define M28 ((1ULL << 28) - 1)
__device__ void scanOcc_dev(const int* __restrict__ cnt, int* __restrict__ rank_,
                            int* __restrict__ cstart, int* __restrict__ rinfo,
                            int* __restrict__ ne, int n, int* tot, int ti, int fo, char* sm) {
    int tid = threadIdx.x;
    int* sbid = (int*)sm;
    ull* sexc = (ull*)(sm + 8);
    ull* wsum = (ull*)(sm + 64);
    ull* woff = (ull*)(sm + 64 + 256);
    int nb = n / 8192;
    while (true) {
        __syncthreads();
        if (tid == 0) *sbid = atomicAdd(&g.tick[ti], 1);
        __syncthreads();
        int bid = *sbid;
        if (bid >= nb) break;
        int base = bid * 8192 + tid * 8;
        ull v[8]; ull t = 0;
#pragma unroll
        for (int j = 0; j < 8; j++) {
            int cv = __ldcg(cnt + base + j);
            ull x = (cv ? 1ULL : 0ULL) | ((ull)(unsigned)cv << 28);
            v[j] = x; t += x;
        }
        ull inc = wscan64(t);
        if ((tid & 31) == 31) wsum[tid >> 5] = inc;
        __syncthreads();
        if (tid < 32) {
            ull x = wsum[tid];
            ull iw = wscan64(x);
            woff[tid] = iw - x;
            ull B = __shfl_sync(FULLM, iw, 31);
            ull* fl = g.scanflags + fo;
            ull exc = 0;
            if (bid == 0) {
                if (tid == 0) atomicExch(&fl[0], (2ULL << 62) | B);
            } else {
                if (tid == 0) atomicExch(&fl[bid], (1ULL << 62) | B);
                int lb = bid - 1;
                while (true) {
                    int idx = lb - tid;
                    ull w = 0; int st = 2;
                    if (idx >= 0) {
                        do { w = atomicAdd(&fl[idx], 0ULL); } while (!(w >> 62));
                        st = (int)(w >> 62);
                    }
                    unsigned pm = __ballot_sync(FULLM, st == 2);
                    ull val = w & ((1ULL << 56) - 1);
                    int firstP = pm ? (__ffs(pm) - 1) : 32;
                    if (tid > firstP) val = 0;
#pragma unroll
                    for (int d = 16; d >= 1; d >>= 1) val += __shfl_xor_sync(FULLM, val, d);
                    exc += val;
                    if (pm) break;
                    lb -= 32;
                }
                if (tid == 0) atomicExch(&fl[bid], (2ULL << 62) | (exc + B));
            }
            if (tid == 0) { *sexc = exc; if (tot && bid == nb - 1) *tot = (int)((exc + B) & M28); }
        }
        __syncthreads();
        ull off = *sexc + woff[tid >> 5] + inc - t;
#pragma unroll
        for (int j = 0; j < 8; j++) {
            int idx = base + j;
            int occ = (int)(v[j] & 1);
            int rk = (int)(off & M28);
            rank_[idx] = rk;
            cstart[idx] = (int)((off >> 28) & M28);
            rinfo[idx] = occ ? rk + 1 : 0;
            if (occ) ne[rk] = idx;
            off += v[j];
        }
    }
}

// ------------------------------------------------------------------ phase bodies
__device__ void foldpre_dev(const float* __restrict__ nodes, int blk, char* sm) {
    int c = blk / 6, kk = blk % 6, kb = kk + 12;
    float scale = __int_as_float((23 - kb + 127) << 23);
    int t = threadIdx.x;
    int s0 = 0, s1 = 0, s2 = 0, tie = 0;
    int mn0 = 0x7f7fffff, mn1 = 0x7f7fffff, mn2 = 0x7f7fffff;
    int mx0 = 0, mx1 = 0, mx2 = 0;
    for (int e = t; e < 2048; e += NTHR) {
        const float* p = nodes + ((size_t)c * 2048 + e) * 10 + 4;
        float r0 = __ldg(p + 0), r1 = __ldg(p + 1), r2 = __ldg(p + 2);
        if (kk == 0) {
            int b0 = __float_as_int(r0), b1 = __float_as_int(r1), b2 = __float_as_int(r2);
            mn0 = min(mn0, b0); mx0 = max(mx0, b0);
            mn1 = min(mn1, b1); mx1 = max(mx1, b1);
            mn2 = min(mn2, b2); mx2 = max(mx2, b2);
        }
        float v0 = __fmul_rn(r0, scale);
        float v1 = __fmul_rn(r1, scale);
        float v2 = __fmul_rn(r2, scale);
        int q0 = __float2int_rn(v0), q1 = __float2int_rn(v1), q2 = __float2int_rn(v2);
        if (fabsf(__fsub_rn(v0, (float)q0)) == 0.5f) tie = 1;
        if (fabsf(__fsub_rn(v1, (float)q1)) == 0.5f) tie = 1;
        if (fabsf(__fsub_rn(v2, (float)q2)) == 0.5f) tie = 1;
        s0 += q0; s1 += q1; s2 += q2;
    }
    s0 = __reduce_add_sync(FULLM, s0);
    s1 = __reduce_add_sync(FULLM, s1);
    s2 = __reduce_add_sync(FULLM, s2);
    tie = __any_sync(FULLM, tie);
    if (kk == 0) {
        mn0 = __reduce_min_sync(FULLM, mn0); mx0 = __reduce_max_sync(FULLM, mx0);
        mn1 = __reduce_min_sync(FULLM, mn1); mx1 = __reduce_max_sync(FULLM, mx1);
        mn2 = __reduce_min_sync(FULLM, mn2); mx2 = __reduce_max_sync(FULLM, mx2);
    }
    int (*sh)[4] = (int(*)[4])sm;
    int wid = t >> 5;
    __syncthreads();
    if ((t & 31) == 0) {
        sh[wid][0] = s0; sh[wid][1] = s1; sh[wid][2] = s2; sh[wid][3] = tie;
        if (kk == 0) {
            atomicMax(&g.mnb[0], 0x7fffffff - mn0); atomicMax(&g.mxb[0], mx0);
            atomicMax(&g.mnb[1], 0x7fffffff - mn1); atomicMax(&g.mxb[1], mx1);
            atomicMax(&g.mnb[2], 0x7fffffff - mn2); atomicMax(&g.mxb[2], mx2);
        }
    }
    __syncthreads();
    if (t == 0) {
        int a0 = 0, a1 = 0, a2 = 0, tt = 0;
        for (int w = 0; w < 32; w++) { a0 += sh[w][0]; a1 += sh[w][1]; a2 += sh[w][2]; tt |= sh[w][3]; }
        g.Stab[(0 * 128 + c) * 6 + kk] = a0;
        g.Stab[(1 * 128 + c) * 6 + kk] = a1;
        g.Stab[(2 * 128 + c) * 6 + kk] = a2;
        g.Ttab[(0 * 128 + c) * 6 + kk] = tt;
        g.Ttab[(1 * 128 + c) * 6 + kk] = tt;
        g.Ttab[(2 * 128 + c) * 6 + kk] = tt;
    }
    __syncthreads();
}

__device__ void fold3b_dev(const float* __restrict__ nodes, char* sm) {
    float* sref = (float*)sm;
    int tid = threadIdx.x;
    if ((tid & 31) == 0 && tid < 96) {
        int d = tid >> 5;
        float s = 0.f;
        for (int c = 0; c < 128; c++) {
            int kb = (__float_as_int(s) >> 23) - 127;
            bool ok = false;
            float cand = 0.f;
            if (s > 0.f && kb >= 12 && kb <= 17) {
                int idx = (d * 128 + c) * 6 + (kb - 12);
                int S = __ldcg(g.Stab + idx);
                int tie = __ldcg(g.Ttab + idx);
                float u = __int_as_float((kb - 23 + 127) << 23);
                cand = __fadd_rn(s, __fmul_rn((float)S, u));
                float lim = __int_as_float((kb + 1 + 127) << 23);
                if (!tie && __fadd_rn(cand, 4.0f) < lim) ok = true;
            }
            if (ok) {
                s = cand;
            } else {
                const float* p = nodes + (size_t)c * 2048 * 10 + 4 + d;
#pragma unroll 8
                for (int e = 0; e < 2048; e++)
                    s = __fadd_rn(s, __ldg(p + e * 10));
            }
        }
        sref[d] = s * (1.0f / 262144.0f);
    }
    __syncthreads();
    float d0 = __fsub_rn(__int_as_float(g.mxb[0]), __int_as_float(0x7fffffff - g.mnb[0]));
    float d1 = __fsub_rn(__int_as_float(g.mxb[1]), __int_as_float(0x7fffffff - g.mnb[1]));
    float d2 = __fsub_rn(__int_as_float(g.mxb[2]), __int_as_float(0x7fffffff - g.mnb[2]));
    float box = fmaxf(d0, fmaxf(d1, d2));
    double half = (double)box * 0.5;
    float hf = (float)half;
    if (tid < 189) {
        int d = tid / 63, i = tid % 63 + 1;
        float r = sref[d];
        float start = __fsub_rn(r, hf);
        float stop  = __fadd_rn(r, hf);
        float delta = __fsub_rn(stop, start);
        float step  = __fmul_rn(delta, 1.0f / 64.0f);
        float b = __fadd_rn(__fmul_rn((float)i, step), start);
        g.bnd[d * 63 + (i - 1)] = b;
    }
    __syncthreads();
}

__device__ __forceinline__ int ub63s(const float* b, float v) {
    int lo = 0, hi = 63;
    while (lo < hi) {
        int m = (lo + hi) >> 1;
        if (b[m] <= v) lo = m + 1; else hi = m;
    }
    return lo;
}

template<int GL, int PGb>
__device__ void mega_dev(const int* __restrict__ nePrev, int npIdx, int nIdx,
                         int* __restrict__ rinfo, int* __restrict__ ne,
                         int* __restrict__ seg, int* __restrict__ ord,
                         int* __restrict__ cntR, int* __restrict__ cstR, char* sm) {
    constexpr int GS = GL * GL * GL;
    constexpr int GLb = (GL == 16) ? 4 : (GL == 8) ? 3 : 2;
    constexpr int PG = 1 << PGb;
    int* sA = (int*)sm;
    int* sB = (int*)sm + GS;
    int* mws = (int*)sm + 2 * GS;
    int* mwo = (int*)sm + 2 * GS + 32;
    int* mtot = (int*)sm + 2 * GS + 64;          // max bytes (2*4096+65)*4 = 33028 < SMBM
    int tid = threadIdx.x;
    int np = ldv(&g.tot[npIdx]);
    for (int i = tid; i < GS; i += NTHR) sA[i] = 0;
    __syncthreads();
    for (int r = tid; r < np; r += NTHR) {
        int e = __ldcg(nePrev + r);
        int c = ((e & (PG - 1)) >> 1) | ((((e >> PGb) & (PG - 1)) >> 1) << GLb)
              | (((e >> (2 * PGb)) >> 1) << (2 * GLb));
        atomicAdd(&sA[c], 1);
    }
    __syncthreads();
    int i0 = tid * 4;
    int p[4]; int tt = 0;
#pragma unroll
    for (int j = 0; j < 4; j++) {
        int q = 0, idx = i0 + j;
        if (idx < GS) { int cv = sA[idx]; q = cv | ((cv > 0) << 16); }
        p[j] = q; tt += q;
    }
    int inc = wscan(tt);
    if ((tid & 31) == 31) mws[tid >> 5] = inc;
    __syncthreads();
    if (tid == 0) {
        int s = 0;
        for (int w = 0; w < 32; w++) { int x = mws[w]; mwo[w] = s; s += x; }
        *mtot = s;
    }
    __syncthreads();
    int exc = mwo[tid >> 5] + inc - tt;
#pragma unroll
    for (int j = 0; j < 4; j++) { int idx = i0 + j; if (idx < GS) sB[idx] = exc; exc += p[j]; }
    if (tid == 0) g.tot[nIdx] = *mtot >> 16;
    __syncthreads();
    for (int c = tid; c < GS; c += NTHR) {
        int cv = sA[c];
        int v = sB[c];
        int rk = v >> 16;
        rinfo[c] = cv ? rk + 1 : 0;
        if (cv) { ne[rk] = c; cntR[rk] = cv; cstR[rk] = v & 0xffff; }
    }
    __syncthreads();
    for (int r = tid; r < np; r += NTHR) {
        int e = __ldcg(nePrev + r);
        int c = ((e & (PG - 1)) >> 1) | ((((e >> PGb) & (PG - 1)) >> 1) << GLb)
              | (((e >> (2 * PGb)) >> 1) << (2 * GLb));
        int v = sB[c];
        seg[r] = v >> 16;
        int old = atomicAdd(&sA[c], 1 << 16);
        ord[(v & 0xffff) + (old >> 16)] = r;
    }
    __syncthreads();
    for (int c = tid; c < GS; c += NTHR) {
        int ncnt = sA[c] & 0xffff;
        if (ncnt >= 2) {
            int* a = ord + (sB[c] & 0xffff);
            for (int i = 1; i < ncnt; i++) {
                int vv = a[i], j = i - 1;
                while (j >= 0 && a[j] > vv) { a[j + 1] = a[j]; j--; }
                a[j + 1] = vv;
            }
        }
    }
    __syncthreads();
}

__device__ __forceinline__ void loadBM(char* sm) {
    int* smBM = (int*)(sm + SMBM);               // [33280, 34144) < SMSZ=34176
    for (int i = threadIdx.x; i < 216; i += NTHR) smBM[i] = __ldcg(g.bmask + i);
    __syncthreads();
}

template<int CG, int FL>
__device__ void ecnt_dev(const int* __restrict__ rinfo, int* __restrict__ ecnt,
                         const int* bm216, int gbase, int gstr) {
    for (int idx = gbase; idx < CG * CG * CG * 27; idx += gstr) {
        int k = idx % 27, q = idx / 27;
        int qx = q % CG, qy = (q / CG) % CG, qz = q / (CG * CG);
        int nx = qx + cNX[k], ny = qy + cNY[k], nz = qz + cNZ[k];
        int c = 0;
        if ((unsigned)nx < (unsigned)CG && (unsigned)ny < (unsigned)CG && (unsigned)nz < (unsigned)CG) {
            const int2* rp = (const int2*)rinfo;
            int aa = 2 * qx + 2 * qy * FL + 2 * qz * FL * FL;
            int bb = 2 * nx + 2 * ny * FL + 2 * nz * FL * FL;
            int2 a01 = __ldg(rp + (aa >> 1));
            int2 a23 = __ldg(rp + ((aa + FL) >> 1));
            int2 a45 = __ldg(rp + ((aa + FL * FL) >> 1));
            int2 a67 = __ldg(rp + ((aa + FL * FL + FL) >> 1));
            int2 b01 = __ldg(rp + (bb >> 1));
            int2 b23 = __ldg(rp + ((bb + FL) >> 1));
            int2 b45 = __ldg(rp + ((bb + FL * FL) >> 1));
            int2 b67 = __ldg(rp + ((bb + FL * FL + FL) >> 1));
            int occB = (b01.x != 0) | ((b01.y != 0) << 1) | ((b23.x != 0) << 2) | ((b23.y != 0) << 3)
                     | ((b45.x != 0) << 4) | ((b45.y != 0) << 5) | ((b67.x != 0) << 6) | ((b67.y != 0) << 7);
            int av[8] = {a01.x, a01.y, a23.x, a23.y, a45.x, a45.y, a67.x, a67.y};
            const int* bm = bm216 + (k << 3);
#pragma unroll
            for (int a = 0; a < 8; a++)
                if (av[a]) c += __popc(bm[a] & occB);
        }
        ecnt[idx] = c;
    }
}

template<int CG, int FL>
__device__ void ewrite_dev(const int* __restrict__ rinfo, const int* __restrict__ eoff,
                           float* __restrict__ out, const int* bm216,
                           int E, int oedge, int gbase, int gstr) {
    for (int idx = gbase; idx < CG * CG * CG * 27; idx += gstr) {
        int k = idx % 27, q = idx / 27;
        int qx = q % CG, qy = (q / CG) % CG, qz = q / (CG * CG);
        int nx = qx + cNX[k], ny = qy + cNY[k], nz = qz + cNZ[k];
        if (!((unsigned)nx < (unsigned)CG && (unsigned)ny < (unsigned)CG && (unsigned)nz < (unsigned)CG))
            continue;
        const int2* rp = (const int2*)rinfo;
        int aa = 2 * qx + 2 * qy * FL + 2 * qz * FL * FL;
        int bb = 2 * nx + 2 * ny * FL + 2 * nz * FL * FL;
        int2 a01 = __ldg(rp + (aa >> 1));
        int2 a23 = __ldg(rp + ((aa + FL) >> 1));
        int2 a45 = __ldg(rp + ((aa + FL * FL) >> 1));
        int2 a67 = __ldg(rp + ((aa + FL * FL + FL) >> 1));
        int2 b01 = __ldg(rp + (bb >> 1));
        int2 b23 = __ldg(rp + ((bb + FL) >> 1));
        int2 b45 = __ldg(rp + ((bb + FL * FL) >> 1));
        int2 b67 = __ldg(rp + ((bb + FL * FL + FL) >> 1));
        int occB = (b01.x != 0) | ((b01.y != 0) << 1) | ((b23.x != 0) << 2) | ((b23.y != 0) << 3)
                 | ((b45.x != 0) << 4) | ((b45.y != 0) << 5) | ((b67.x != 0) << 6) | ((b67.y != 0) << 7);
        int av[8] = {a01.x, a01.y, a23.x, a23.y, a45.x, a45.y, a67.x, a67.y};
        int rv[8] = {b01.x, b01.y, b23.x, b23.y, b45.x, b45.y, b67.x, b67.y};
        float* o0 = out + oedge + __ldcg(eoff + idx);
#pragma unroll
        for (int a = 0; a < 8; a++) {
            if (av[a]) {
                float ra = (float)(av[a] - 1);
                int m = bm216[(k << 3) | a] & occB;
                while (m) {
                    int b = __ffs(m) - 1;
                    m &= m - 1;
                    o0[0] = (float)(rv[b] - 1);
                    o0[E] = ra;
                    o0++;
                }
            }
        }
    }
}

// ------------------------------------------------------------------ the megakernel
__global__ void __launch_bounds__(NTHR, 1) k_megaAll(const float* __restrict__ nodes,
                                                     float* __restrict__ out) {
    __shared__ __align__(16) char sm[SMSZ];
    int tid = threadIdx.x, bid = blockIdx.x;
    int gt = bid * NTHR + tid;
    int barn = 0;
#define GBAR() do { barn++; __syncthreads(); if (tid == 0) { __threadfence(); \
    atomicAdd(&g.barcnt, 1); \
    while (atomicAdd(&g.barcnt, 0) < NBLK * barn) __nanosleep(64); \
    __threadfence(); } __syncthreads(); } while (0)

    const int EOFF1 = 884736, EOFF2 = 995328, EOFF3 = 1009152, EOFF4 = 1010880;
    const int ETOT = 1011096;
    int* smBM = (int*)(sm + SMBM);

    // P0: bmask (block 0) + foldpre (768 virtual blocks)
    if (bid == 0 && tid < 216) {
        int k = tid >> 3, a = tid & 7;
        int ox = cNX[k], oy = cNY[k], oz = cNZ[k];
        int ax = a & 1, ay = (a >> 1) & 1, az = a >> 2;
        int m = 0;
        for (int b = 0; b < 8; b++) {
            int dx = 2 * ox + (b & 1) - ax;
            int dy = 2 * oy + ((b >> 1) & 1) - ay;
            int dz = 2 * oz + (b >> 2) - az;
            if (dx > 1 || dx < -1 || dy > 1 || dy < -1 || dz > 1 || dz < -1) m |= 1 << b;
        }
        g.bmask[tid] = m;
    }
    for (int vb = bid; vb < 768; vb += NBLK) foldpre_dev(nodes, vb, sm);
    GBAR();

    // P1: exact fold + bounds (block 0)
    if (bid == 0) fold3b_dev(nodes, sm);
    GBAR();

    // P2: cells (bnd staged to shared via L2)
    {
        float* sbnd = (float*)sm;
        for (int i = tid; i < 189; i += NTHR)
            sbnd[i] = __int_as_float(__ldcg((const int*)g.bnd + i));
        __syncthreads();
        for (int i = gt; i < NPT; i += GSTRIDE) {
            float x = nodes[i * 10 + 4], y = nodes[i * 10 + 5], z = nodes[i * 10 + 6];
            int xg = ub63s(sbnd, x);
            int yg = 63 - ub63s(sbnd + 63, y);
            int zg = 63 - ub63s(sbnd + 126, z);
            int c = xg + (yg << 6) + (zg << 12);
            g.cid[i] = c;
            atomicAdd(&g.cnt0[c], 1);
        }
    }
    GBAR();

    // P3: level-0 occupancy scan
    scanOcc_dev(g.cnt0, g.rank0, g.cstart0, g_rinfo0, g.neA, C0, &g.tot[0], 0, 0, sm);
    GBAR();

    // P4: scatter + seg + pdeg
    for (int i = gt; i < NPT; i += GSTRIDE) {
        int c = g.cid[i];
        int slot = g.cstart0[c] + atomicAdd(&g.cur0[c], 1);
        g.order0[slot] = i;
        g.seg0[i] = g.rank0[c];
        int x = c & 63, y = (c >> 6) & 63, z = c >> 12;
        int d = 0;
#pragma unroll
        for (int k = 0; k < 27; k++) {
            int nx = x + cNX[k], ny = y + cNY[k], nz = z + cNZ[k];
            if ((unsigned)nx < 64u && (unsigned)ny < 64u && (unsigned)nz < 64u)
                d += g.cnt0[nx + (ny << 6) + (nz << 12)];
        }
        g.pdeg[i] = d;
    }
    GBAR();

    // P5: sort0 + pdeg scan + ecnt L0 + l1occup
    for (int c = gt; c < C0; c += GSTRIDE) {
        int n = g.cnt0[c];
        if (n >= 2) {
            int* a = g.order0 + g.cstart0[c];
            for (int i = 1; i < n; i++) {
                int v = __ldcg(a + i), j = i - 1;
                while (j >= 0 && __ldcg(a + j) > v) { a[j + 1] = __ldcg(a + j); j--; }
                a[j + 1] = v;
            }
        }
    }
    scan1_dev(g.pdeg, g.poff, NPT, &g.tot[5], 1, 64, sm);
    loadBM(sm);
    ecnt_dev<32, 64>(g_rinfo0, g_ecnt8, smBM, gt, GSTRIDE);
    {
        int n0 = ldv(&g.tot[0]);
        for (int r = gt; r < n0; r += GSTRIDE) {
            int e = g.neA[r];
            int cc = ((e & 63) >> 1) | ((((e >> 6) & 63) >> 1) << 5) | (((e >> 12) >> 1) << 10);
            atomicAdd(&g.cntLcell[cc], 1);
        }
    }
    GBAR();

    // P6: level-1 occupancy scan + sv0 segmented + graph write
    scanOcc_dev(g.cntLcell, g.rankL, g.cstartLcell, g_rinfoL, g.neA + 262144,
                32768, &g.tot[1], 2, 128, sm);
    {
        int n0 = ldv(&g.tot[0]);
        for (int r = gt; r < n0; r += GSTRIDE) {
            int c = g.neA[r];
            int n = g.cnt0[c];
            int b = g.cstart0[c];
            float acc[10];
#pragma unroll
            for (int j = 0; j < 10; j++) acc[j] = 0.f;
            for (int t2 = 0; t2 < n; t2++) {
                int i = __ldcg(g.order0 + b + t2);
                const float* row = nodes + (size_t)i * 10;
                float m = row[0];
                acc[0] += m;
#pragma unroll
                for (int j = 1; j < 10; j++) acc[j] += m * row[j];
            }
            float* o = g_svraw + (size_t)r * 10;
#pragma unroll
            for (int j = 0; j < 10; j++) o[j] = acc[j];
        }
    }
    {
        int T = ldv(&g.tot[5]);
        for (int i = gt; i < NPT; i += GSTRIDE) {
            int c = g.cid[i];
            int x = c & 63, y = (c >> 6) & 63, z = c >> 12;
            int col = g.poff[i];
            float fi = (float)i;
            for (int k = 0; k < 27; k++) {
                int nx = x + cNX[k], ny = y + cNY[k], nz = z + cNZ[k];
                if ((unsigned)nx < 64u && (unsigned)ny < 64u && (unsigned)nz < 64u) {
                    int cc = nx + (ny << 6) + (nz << 12);
                    int n = g.cnt0[cc];
                    if (n) {
                        int b = g.cstart0[cc];
                        for (int t2 = 0; t2 < n; t2++) {
                            out[col] = (float)__ldcg(g.order0 + b + t2);
                            out[T + col] = fi;
                            col++;
                        }
                    }
                }
            }
        }
    }
    GBAR();

    // P7: level-1 seg + scatter
    {
        int n0 = ldv(&g.tot[0]);
        for (int r = gt; r < n0; r += GSTRIDE) {
            int e = g.neA[r];
            int cc = ((e & 63) >> 1) | ((((e >> 6) & 63) >> 1) << 5) | (((e >> 12) >> 1) << 10);
            g.segL[r] = g.rankL[cc];
            int slot = g.cstartLcell[cc] + atomicAdd(&g.curL[cc], 1);
            g.ordL[slot] = r;
        }
    }
    GBAR();

    // P8: level-1 sort + cntR/cstR export + ecnt L1
    {
        int n1 = ldv(&g.tot[1]);
        for (int s = gt; s < n1; s += GSTRIDE) {
            int cc = g.neA[262144 + s];
            int n = g.cntLcell[cc];
            int b = g.cstartLcell[cc];
            g.cntR[s] = n;
            g.cstR[s] = b;
            if (n >= 2) {
                int* a = g.ordL + b;
                for (int i = 1; i < n; i++) {
                    int v = __ldcg(a + i), j = i - 1;
                    while (j >= 0 && __ldcg(a + j) > v) { a[j + 1] = __ldcg(a + j); j--; }
                    a[j + 1] = v;
                }
            }
        }
    }
    loadBM(sm);
    ecnt_dev<16, 32>(g_rinfoL, g_ecnt8 + EOFF1, smBM, gt, GSTRIDE);
    GBAR();

    // P9: mega level 2 (block 0) + svagg level 1 (other blocks)
    if (bid == 0) {
        mega_dev<16, 5>(g.neA + 262144, 1, 2, g_rinfoL + 32768, g.neA + 294912,
                        g.segL + 262144, g.ordL + 262144, g.cntR + 32768, g.cstR + 32768, sm);
    } else {
        int n1 = ldv(&g.tot[1]);
        for (int s = (bid - 1) * NTHR + tid; s < n1; s += (NBLK - 1) * NTHR) {
            int n = g.cntR[s], b = g.cstR[s];
            float acc[10];
#pragma unroll
            for (int j = 0; j < 10; j++) acc[j] = 0.f;
            for (int t2 = 0; t2 < n; t2++) {
                const float* row = g_svraw + (size_t)__ldcg(g.ordL + b + t2) * 10;
#pragma unroll
                for (int j = 0; j < 10; j++) acc[j] += row[j];
            }
            float* o = g_svraw + (size_t)(262144 + s) * 10;
#pragma unroll
            for (int j = 0; j < 10; j++) o[j] = acc[j];
        }
    }
    GBAR();

    // P10: mega level 3 (block 0) + ecnt L2 + svagg level 2 (other blocks)
    if (bid == 0) {
        mega_dev<8, 4>(g.neA + 294912, 2, 3, g_rinfoL + 36864, g.neA + 299008,
                       g.segL + 294912, g.ordL + 294912, g.cntR + 36864, g.cstR + 36864, sm);
    } else {
        int gb = (bid - 1) * NTHR + tid, gs = (NBLK - 1) * NTHR;
        loadBM(sm);
        ecnt_dev<8, 16>(g_rinfoL + 32768, g_ecnt8 + EOFF2, smBM, gb, gs);
        int n2 = ldv(&g.tot[2]);
        for (int s = gb; s < n2; s += gs) {
            int n = g.cntR[32768 + s], b = g.cstR[32768 + s];
            float acc[10];
#pragma unroll
            for (int j = 0; j < 10; j++) acc[j] = 0.f;
            for (int t2 = 0; t2 < n; t2++) {
                const float* row = g_svraw + (size_t)(262144 + __ldcg(g.ordL + 262144 + b + t2)) * 10;
#pragma unroll
                for (int j = 0; j < 10; j++) acc[j] += row[j];
            }
            float* o = g_svraw + (size_t)(294912 + s) * 10;
#pragma unroll
            for (int j = 0; j < 10; j++) o[j] = acc[j];
        }
    }
    GBAR();

    // P11: mega level 4 (block 0) + ecnt L3 + svagg level 3 (other blocks)
    if (bid == 0) {
        mega_dev<4, 3>(g.neA + 299008, 3, 4, g_rinfoL + 37376, g.neA + 299520,
                       g.segL + 299008, g.ordL + 299008, g.cntR + 37376, g.cstR + 37376, sm);
    } else {
        int gb = (bid - 1) * NTHR + tid, gs = (NBLK - 1) * NTHR;
        loadBM(sm);
        ecnt_dev<4, 8>(g_rinfoL + 36864, g_ecnt8 + EOFF3, smBM, gb, gs);
        int n3 = ldv(&g.tot[3]);
        for (int s = gb; s < n3; s += gs) {
            int n = g.cntR[36864 + s], b = g.cstR[36864 + s];
            float acc[10];
#pragma unroll
            for (int j = 0; j < 10; j++) acc[j] = 0.f;
            for (int t2 = 0; t2 < n; t2++) {
                const float* row = g_svraw + (size_t)(294912 + __ldcg(g.ordL + 294912 + b + t2)) * 10;
#pragma unroll
                for (int j = 0; j < 10; j++) acc[j] += row[j];
            }
            float* o = g_svraw + (size_t)(299008 + s) * 10;
#pragma unroll
            for (int j = 0; j < 10; j++) o[j] = acc[j];
        }
    }
    GBAR();

    // P12: ecnt L4 + svagg level 4
    loadBM(sm);
    ecnt_dev<2, 4>(g_rinfoL + 37376, g_ecnt8 + EOFF4, smBM, gt, GSTRIDE);
    {
        int n4 = ldv(&g.tot[4]);
        for (int s = gt; s < n4; s += GSTRIDE) {
            int n = g.cntR[37376 + s], b = g.cstR[37376 + s];
            float acc[10];
#pragma unroll
            for (int j = 0; j < 10; j++) acc[j] = 0.f;
            for (int t2 = 0; t2 < n; t2++) {
                const float* row = g_svraw + (size_t)(299008 + __ldcg(g.ordL + 299008 + b + t2)) * 10;
#pragma unroll
                for (int j = 0; j < 10; j++) acc[j] += row[j];
            }
            float* o = g_svraw + (size_t)(299520 + s) * 10;
#pragma unroll
            for (int j = 0; j < 10; j++) o[j] = acc[j];
        }
    }
    GBAR();

    // P13: edge scan (concatenated)
    scan1_dev(g_ecnt8, g_eoff8, ETOT, &g.tot[6], 3, 256, sm);
    GBAR();

    // P14: layout
    if (bid == 0 && tid == 0) {
        int n0 = ldv(&g.tot[0]), n1 = ldv(&g.tot[1]), n2 = ldv(&g.tot[2]);
        int n3 = ldv(&g.tot[3]), n4 = ldv(&g.tot[4]);
        int T = ldv(&g.tot[5]), E = ldv(&g.tot[6]);
        int A = NPT + n0 + n1 + n2 + n3;
        int S = n0 + n1 + n2 + n3 + n4;
        g.A = A; g.S = S; g.E = E;
        g.oassign = 2 * T;
        g.osv = 2 * T + 2 * A;
        g.oedge = g.osv + 10 * S;
        g.oids = g.oedge + 2 * E;
        g.svb[0] = 0; g.svb[1] = n0; g.svb[2] = n0 + n1; g.svb[3] = n0 + n1 + n2; g.svb[4] = n0 + n1 + n2 + n3;
        g.ab[0] = 0; g.ab[1] = NPT; g.ab[2] = NPT + n0; g.ab[3] = NPT + n0 + n1; g.ab[4] = NPT + n0 + n1 + n2;
    }
    GBAR();

    // P15: assigns + sv/id + edge writes
    {
        loadBM(sm);
        int A = ldv(&g.A);
        int oassign = ldv(&g.oassign);
        int ab1 = ldv(&g.ab[1]), ab2 = ldv(&g.ab[2]), ab3 = ldv(&g.ab[3]), ab4 = ldv(&g.ab[4]);
        for (int t2 = gt; t2 < A; t2 += GSTRIDE) {
            const int* ord; const int* seg; int loc;
            if (t2 < ab1)      { ord = g.order0;          seg = g.seg0;            loc = t2; }
            else if (t2 < ab2) { ord = g.ordL + 0;        seg = g.segL + 0;        loc = t2 - ab1; }
            else if (t2 < ab3) { ord = g.ordL + 262144;   seg = g.segL + 262144;   loc = t2 - ab2; }
            else if (t2 < ab4) { ord = g.ordL + 294912;   seg = g.segL + 294912;   loc = t2 - ab3; }
            else               { ord = g.ordL + 299008;   seg = g.segL + 299008;   loc = t2 - ab4; }
            int p = __ldcg(ord + loc);
            out[oassign + t2] = (float)__ldcg(seg + p);
            out[oassign + A + t2] = (float)p;
        }
        int S = ldv(&g.S);
        int osv = ldv(&g.osv), oids = ldv(&g.oids);
        int sb1 = ldv(&g.svb[1]), sb2 = ldv(&g.svb[2]), sb3 = ldv(&g.svb[3]), sb4 = ldv(&g.svb[4]);
        for (int r = gt; r < S; r += GSTRIDE) {
            int neo;
            if (r < sb1)      neo = 0;
            else if (r < sb2) neo = 262144 - sb1;
            else if (r < sb3) neo = 294912 - sb2;
            else if (r < sb4) neo = 299008 - sb3;
            else              neo = 299520 - sb4;
            int loc = neo + r;
            out[oids + r] = (float)__ldcg(g.neA + loc);
            const float* raw = g_svraw + (size_t)loc * 10;
            float m = raw[0];
            float* o = out + osv + (size_t)r * 10;
            o[0] = m;
#pragma unroll
            for (int j = 1; j < 10; j++) o[j] = raw[j] / m;
        }
        int E = ldv(&g.E), oedge = ldv(&g.oedge);
        ewrite_dev<32, 64>(g_rinfo0,         g_eoff8,         out, smBM, E, oedge, gt, GSTRIDE);
        ewrite_dev<16, 32>(g_rinfoL,         g_eoff8 + EOFF1, out, smBM, E, oedge, gt, GSTRIDE);
        ewrite_dev<8, 16>(g_rinfoL + 32768,  g_eoff8 + EOFF2, out, smBM, E, oedge, gt, GSTRIDE);
        ewrite_dev<4, 8>(g_rinfoL + 36864,   g_eoff8 + EOFF3, out, smBM, E, oedge, gt, GSTRIDE);
        ewrite_dev<2, 4>(g_rinfoL + 37376,   g_eoff8 + EOFF4, out, smBM, E, oedge, gt, GSTRIDE);
    }
#undef GBAR
}

// ------------------------------------------------------------------ host
extern "C" void kernel_launch(void* const* d_in, const int* in_sizes, int n_in,
                              void* d_out, int out_size) {
    const float* nodes = (const float*)d_in[0];
    float* out = (float*)d_out;
    GG* G;
    cudaGetSymbolAddress((void**)&G, g);
    cudaMemsetAsync(G, 0, offsetof(GG, zend), 0);
    k_megaAll<<<NBLK, NTHR>>>(nodes, out);
    (void)in_sizes; (void)n_in; (void)out_size;
}

// round 15
// speedup vs baseline: 1.0679x; 1.0679x over previous
#include <cuda_runtime.h>
#include <cstdint>
#include <cstddef>

#define NPT 262144
#define C0  262144
#define FULLM 0xffffffffu
typedef unsigned long long ull;

__constant__ int cNX[27] = {-1,0,1,-1,0,1,-1,0,1,-1,0,1,-1,0,1,-1,0,1,-1,0,1,-1,0,1,-1,0,1};
__constant__ int cNY[27] = {-1,-1,-1,0,0,0,1,1,1,-1,-1,-1,0,0,0,1,1,1,-1,-1,-1,0,0,0,1,1,1};
__constant__ int cNZ[27] = {-1,-1,-1,-1,-1,-1,-1,-1,-1,0,0,0,0,0,0,0,0,0,1,1,1,1,1,1,1,1,1};

struct __align__(256) GG {
    // ---------- zero block (memset each launch, ~2.4MB) ----------
    int   cnt0[C0];
    int   cur0[C0];
    int   cntLcell[32768];
    int   curL[32768];
    int   tick[16];
    ull   scanflags[2304];
    int   tot[16];          // 0..4 = n_l, 5 = T, 6 = E
    int   mnb[4], mxb[4];   // mnb stores (0x7fffffff - bits) under atomicMax
    int   zend[4];
    // ---------- rest ----------
    int   cid[NPT];
    int   rank0[C0];
    int   cstart0[C0];
    int   order0[NPT];
    int   seg0[NPT];
    int   pdeg[NPT];
    int   poff[NPT];
    int   neA[299584];
    int   rankL[32768];
    int   cstartLcell[32768];
    int   segL[299520];
    int   ordL[299520];
    int   cntR[37440];
    int   cstR[37440];
    int   bmask[216];
    int   Stab[3 * 128 * 6];
    int   Ttab[3 * 128 * 6];
    float bnd[3 * 63];
    int oassign, osv, oedge, oids, A, S, E;
    int svb[5], ab[5];
};
__device__ GG g;

__device__ __align__(128) int g_rinfo0[C0];
__device__ __align__(128) int g_rinfoL[37440];
__device__ __align__(128) int g_ecnt8[1011200];
__device__ __align__(128) int g_eoff8[1011200];
__device__ __align__(128) int g_tmpc[C0];
__device__ float g_svraw[299584 * 10];

// ------------------------------------------------------------------ scan utils
__device__ __forceinline__ int wscan(int x) {
    int lane = threadIdx.x & 31;
#pragma unroll
    for (int d = 1; d < 32; d <<= 1) {
        int y = __shfl_up_sync(FULLM, x, d);
        if (lane >= d) x += y;
    }
    return x;
}
__device__ __forceinline__ ull wscan64(ull x) {
    int lane = threadIdx.x & 31;
#pragma unroll
    for (int d = 1; d < 32; d <<= 1) {
        ull y = __shfl_up_sync(FULLM, x, d);
        if (lane >= d) x += y;
    }
    return x;
}

__global__ void __launch_bounds__(512) k_scan1(const int* __restrict__ in, int* __restrict__ out,
                                               int n, int* tot, int ti, int fo) {
    __shared__ int sbid, sexc;
    __shared__ int wsum[16], woff[16];
    int tid = threadIdx.x;
    if (tid == 0) sbid = atomicAdd(&g.tick[ti], 1);
    __syncthreads();
    int bid = sbid;
    int base = bid * 8192 + tid * 16;
    int v[16]; int t = 0;
    if (base + 16 <= n) {
        const int4* p = (const int4*)(in + base);
#pragma unroll
        for (int j = 0; j < 4; j++) {
            int4 x = __ldg(p + j);
            v[4*j] = x.x; v[4*j+1] = x.y; v[4*j+2] = x.z; v[4*j+3] = x.w;
        }
    } else {
#pragma unroll
        for (int j = 0; j < 16; j++) v[j] = (base + j < n) ? in[base + j] : 0;
    }
#pragma unroll
    for (int j = 0; j < 16; j++) t += v[j];
    int inc = wscan(t);
    if ((tid & 31) == 31) wsum[tid >> 5] = inc;
    __syncthreads();
    if (tid < 32) {
        int x = (tid < 16) ? wsum[tid] : 0;
        int iw = wscan(x);
        if (tid < 16) woff[tid] = iw - x;
        int B = __shfl_sync(FULLM, iw, 15);
        ull* fl = g.scanflags + fo;
        int exc = 0;
        if (bid == 0) {
            if (tid == 0) atomicExch(&fl[0], (2ULL << 62) | (unsigned)B);
        } else {
            if (tid == 0) atomicExch(&fl[bid], (1ULL << 62) | (unsigned)B);
            int lb = bid - 1;
            while (true) {
                int idx = lb - tid;
                ull w = 0; int st = 2;
                if (idx >= 0) {
                    do { w = atomicAdd(&fl[idx], 0ULL); } while (!(w >> 62));
                    st = (int)(w >> 62);
                }
                unsigned pm = __ballot_sync(FULLM, st == 2);
                int val = (int)(unsigned)w;
                int firstP = pm ? (__ffs(pm) - 1) : 32;
                if (tid > firstP) val = 0;
#pragma unroll
                for (int d = 16; d >= 1; d >>= 1) val += __shfl_xor_sync(FULLM, val, d);
                exc += val;
                if (pm) break;
                lb -= 32;
            }
            if (tid == 0) atomicExch(&fl[bid], (2ULL << 62) | (unsigned)(exc + B));
        }
        if (tid == 0) { sexc = exc; if (tot && bid == (int)gridDim.x - 1) *tot = exc + B; }
    }
    __syncthreads();
    int off = sexc + woff[tid >> 5] + inc - t;
    if (base + 16 <= n) {
        int4* q = (int4*)(out + base);
#pragma unroll
        for (int j = 0; j < 4; j++) {
            int4 x;
            x.x = off; off += v[4*j];
            x.y = off; off += v[4*j+1];
            x.z = off; off += v[4*j+2];
            x.w = off; off += v[4*j+3];
            q[j] = x;
        }
    } else {
        for (int j = 0; j < 16; j++) { if (base + j < n) out[base + j] = off; off += v[j]; }
    }
}

// occupancy scan: packed dual scan of (occ = cnt>0, cnt); emits rank, cstart, rinfo, ne, tot
#define M28 ((1ULL << 28) - 1)
__global__ void __launch_bounds__(512) k_scanOcc(const int* __restrict__ cnt,
                                                 int* __restrict__ rank_, int* __restrict__ cstart,
                                                 int* __restrict__ rinfo, int* __restrict__ ne,
                                                 int n, int* tot, int ti, int fo) {
    __shared__ int sbid;
    __shared__ ull sexc2;
    __shared__ ull wsum[16], woff[16];
    int tid = threadIdx.x;
    if (tid == 0) sbid = atomicAdd(&g.tick[ti], 1);
    __syncthreads();
    int bid = sbid;
    int base = bid * 8192 + tid * 16;
    ull v[16]; ull t = 0;
#pragma unroll
    for (int j = 0; j < 16; j++) {
        int cv = __ldg(cnt + base + j);
        ull x = (cv ? 1ULL : 0ULL) | ((ull)(unsigned)cv << 28);
        v[j] = x; t += x;
    }
    ull inc = wscan64(t);
    if ((tid & 31) == 31) wsum[tid >> 5] = inc;
    __syncthreads();
    if (tid < 32) {
        ull x = (tid < 16) ? wsum[tid] : 0;
        ull iw = wscan64(x);
        if (tid < 16) woff[tid] = iw - x;
        ull B = __shfl_sync(FULLM, iw, 15);
        ull* fl = g.scanflags + fo;
        ull exc = 0;
        if (bid == 0) {
            if (tid == 0) atomicExch(&fl[0], (2ULL << 62) | B);
        } else {
            if (tid == 0) atomicExch(&fl[bid], (1ULL << 62) | B);
            int lb = bid - 1;
            while (true) {
                int idx = lb - tid;
                ull w = 0; int st = 2;
                if (idx >= 0) {
                    do { w = atomicAdd(&fl[idx], 0ULL); } while (!(w >> 62));
                    st = (int)(w >> 62);
                }
                unsigned pm = __ballot_sync(FULLM, st == 2);
                ull val = w & ((1ULL << 56) - 1);
                int firstP = pm ? (__ffs(pm) - 1) : 32;
                if (tid > firstP) val = 0;
#pragma unroll
                for (int d = 16; d >= 1; d >>= 1) val += __shfl_xor_sync(FULLM, val, d);
                exc += val;
                if (pm) break;
                lb -= 32;
            }
            if (tid == 0) atomicExch(&fl[bid], (2ULL << 62) | (exc + B));
        }
        if (tid == 0) { sexc2 = exc; if (tot && bid == (int)gridDim.x - 1) *tot = (int)((exc + B) & M28); }
    }
    __syncthreads();
    ull off = sexc2 + woff[tid >> 5] + inc - t;
#pragma unroll
    for (int j = 0; j < 16; j++) {
        int idx = base + j;
        int occ = (int)(v[j] & 1);
        int rk = (int)(off & M28);
        rank_[idx] = rk;
        cstart[idx] = (int)((off >> 28) & M28);
        rinfo[idx] = occ ? rk + 1 : 0;
        if (occ) ne[rk] = idx;
        off += v[j];
    }
}

// ------------------------------------------------------------------ stage A
__global__ void k_init2() {
    int t = threadIdx.x;
    if (t < 216) {
        int k = t >> 3, a = t & 7;
        int ox = cNX[k], oy = cNY[k], oz = cNZ[k];
        int ax = a & 1, ay = (a >> 1) & 1, az = a >> 2;
        int m = 0;
        for (int b = 0; b < 8; b++) {
            int dx = 2 * ox + (b & 1) - ax;
            int dy = 2 * oy + ((b >> 1) & 1) - ay;
            int dz = 2 * oz + (b >> 2) - az;
            if (dx > 1 || dx < -1 || dy > 1 || dy < -1 || dz > 1 || dz < -1) m |= 1 << b;
        }
        g.bmask[t] = m;
    }
}

__global__ void __launch_bounds__(256) k_foldpre(const float* __restrict__ nodes) {
    int blk = blockIdx.x;
    int c = blk / 6, kk = blk % 6, kb = kk + 12;
    float scale = __int_as_float((23 - kb + 127) << 23);
    int t = threadIdx.x;
    int s0 = 0, s1 = 0, s2 = 0, tie = 0;
    int mn0 = 0x7f7fffff, mn1 = 0x7f7fffff, mn2 = 0x7f7fffff;
    int mx0 = 0, mx1 = 0, mx2 = 0;
    for (int e = t; e < 2048; e += 256) {
        const float* p = nodes + ((size_t)c * 2048 + e) * 10 + 4;
        float r0 = __ldg(p + 0), r1 = __ldg(p + 1), r2 = __ldg(p + 2);
        if (kk == 0) {
            int b0 = __float_as_int(r0), b1 = __float_as_int(r1), b2 = __float_as_int(r2);
            mn0 = min(mn0, b0); mx0 = max(mx0, b0);
            mn1 = min(mn1, b1); mx1 = max(mx1, b1);
            mn2 = min(mn2, b2); mx2 = max(mx2, b2);
        }
        float v0 = __fmul_rn(r0, scale);
        float v1 = __fmul_rn(r1, scale);
        float v2 = __fmul_rn(r2, scale);
        int q0 = __float2int_rn(v0), q1 = __float2int_rn(v1), q2 = __float2int_rn(v2);
        if (fabsf(__fsub_rn(v0, (float)q0)) == 0.5f) tie = 1;
        if (fabsf(__fsub_rn(v1, (float)q1)) == 0.5f) tie = 1;
        if (fabsf(__fsub_rn(v2, (float)q2)) == 0.5f) tie = 1;
        s0 += q0; s1 += q1; s2 += q2;
    }
    s0 = __reduce_add_sync(FULLM, s0);
    s1 = __reduce_add_sync(FULLM, s1);
    s2 = __reduce_add_sync(FULLM, s2);
    tie = __any_sync(FULLM, tie);
    if (kk == 0) {
        mn0 = __reduce_min_sync(FULLM, mn0); mx0 = __reduce_max_sync(FULLM, mx0);
        mn1 = __reduce_min_sync(FULLM, mn1); mx1 = __reduce_max_sync(FULLM, mx1);
        mn2 = __reduce_min_sync(FULLM, mn2); mx2 = __reduce_max_sync(FULLM, mx2);
    }
    __shared__ int sh[8][4];
    int wid = t >> 5;
    if ((t & 31) == 0) {
        sh[wid][0] = s0; sh[wid][1] = s1; sh[wid][2] = s2; sh[wid][3] = tie;
        if (kk == 0) {
            atomicMax(&g.mnb[0], 0x7fffffff - mn0); atomicMax(&g.mxb[0], mx0);
            atomicMax(&g.mnb[1], 0x7fffffff - mn1); atomicMax(&g.mxb[1], mx1);
            atomicMax(&g.mnb[2], 0x7fffffff - mn2); atomicMax(&g.mxb[2], mx2);
        }
    }
    __syncthreads();
    if (t == 0) {
        int a0 = 0, a1 = 0, a2 = 0, tt = 0;
        for (int w = 0; w < 8; w++) { a0 += sh[w][0]; a1 += sh[w][1]; a2 += sh[w][2]; tt |= sh[w][3]; }
        g.Stab[(0 * 128 + c) * 6 + kk] = a0;
        g.Stab[(1 * 128 + c) * 6 + kk] = a1;
        g.Stab[(2 * 128 + c) * 6 + kk] = a2;
        g.Ttab[(0 * 128 + c) * 6 + kk] = tt;
        g.Ttab[(1 * 128 + c) * 6 + kk] = tt;
        g.Ttab[(2 * 128 + c) * 6 + kk] = tt;
    }
}

__global__ void k_fold3b(const float* __restrict__ nodes) {
    __shared__ float sref[3];
    int tid = threadIdx.x;
    if ((tid & 31) == 0 && tid < 96) {
        int d = tid >> 5;
        float s = 0.f;
        for (int c = 0; c < 128; c++) {
            int kb = (__float_as_int(s) >> 23) - 127;
            bool ok = false;
            float cand = 0.f;
            if (s > 0.f && kb >= 12 && kb <= 17) {
                int idx = (d * 128 + c) * 6 + (kb - 12);
                int S = g.Stab[idx];
                int tie = g.Ttab[idx];
                float u = __int_as_float((kb - 23 + 127) << 23);
                cand = __fadd_rn(s, __fmul_rn((float)S, u));
                float lim = __int_as_float((kb + 1 + 127) << 23);
                if (!tie && __fadd_rn(cand, 4.0f) < lim) ok = true;
            }
            if (ok) {
                s = cand;
            } else {
                const float* p = nodes + (size_t)c * 2048 * 10 + 4 + d;
#pragma unroll 8
                for (int e = 0; e < 2048; e++)
                    s = __fadd_rn(s, __ldg(p + e * 10));
            }
        }
        sref[d] = s * (1.0f / 262144.0f);
    }
    __syncthreads();
    float d0 = __fsub_rn(__int_as_float(g.mxb[0]), __int_as_float(0x7fffffff - g.mnb[0]));
    float d1 = __fsub_rn(__int_as_float(g.mxb[1]), __int_as_float(0x7fffffff - g.mnb[1]));
    float d2 = __fsub_rn(__int_as_float(g.mxb[2]), __int_as_float(0x7fffffff - g.mnb[2]));
    float box = fmaxf(d0, fmaxf(d1, d2));
    double half = (double)box * 0.5;
    float hf = (float)half;
    for (int t = tid; t < 189; t += 128) {
        int d = t / 63, i = t % 63 + 1;
        float r = sref[d];
        float start = __fsub_rn(r, hf);
        float stop  = __fadd_rn(r, hf);
        float delta = __fsub_rn(stop, start);
        float step  = __fmul_rn(delta, 1.0f / 64.0f);
        float b = __fadd_rn(__fmul_rn((float)i, step), start);
        g.bnd[d * 63 + (i - 1)] = b;
    }
}

__device__ __forceinline__ int ub63(const float* __restrict__ b, float v) {
    int lo = 0, hi = 63;
    while (lo < hi) {
        int m = (lo + hi) >> 1;
        if (b[m] <= v) lo = m + 1; else hi = m;
    }
    return lo;
}

__global__ void k_cells(const float* __restrict__ nodes) {
    int i = blockIdx.x * blockDim.x + threadIdx.x;
    if (i >= NPT) return;
    float x = nodes[i * 10 + 4], y = nodes[i * 10 + 5], z = nodes[i * 10 + 6];
    int xg = ub63(g.bnd, x);
    int yg = 63 - ub63(g.bnd + 63, y);
    int zg = 63 - ub63(g.bnd + 126, z);
    int c = xg + (yg << 6) + (zg << 12);
    g.cid[i] = c;
    atomicAdd(&g.cnt0[c], 1);
}

// separable 3x3x3 box filter over the 64^3 cell grid (shift = 0, 6, 12)
__global__ void k_conv(const int* __restrict__ in, int* __restrict__ outp, int shift) {
    int c = blockIdx.x * blockDim.x + threadIdx.x;
    if (c >= C0) return;
    int coord = (c >> shift) & 63;
    int stride = 1 << shift;
    int s = in[c];
    if (coord > 0) s += in[c - stride];
    if (coord < 63) s += in[c + stride];
    outp[c] = s;
}

__global__ void k_scatseg() {
    int i = blockIdx.x * blockDim.x + threadIdx.x;
    if (i >= NPT) return;
    int c = g.cid[i];
    int slot = g.cstart0[c] + atomicAdd(&g.cur0[c], 1);
    g.order0[slot] = i;
    g.seg0[i] = g.rank0[c];
    g.pdeg[i] = g_ecnt8[c];     // deg_cell from separable convolution
}

__global__ void k_sort0() {
    int c = blockIdx.x * blockDim.x + threadIdx.x;
    if (c >= C0) return;
    int n = g.cnt0[c];
    if (n < 2) return;
    int* a = g.order0 + g.cstart0[c];
    for (int i = 1; i < n; i++) {
        int v = a[i], j = i - 1;
        while (j >= 0 && a[j] > v) { a[j + 1] = a[j]; j--; }
        a[j + 1] = v;
    }
}

// warp-cooperative graph write: one warp per point, lane k = neighbor cell k
__global__ void __launch_bounds__(256) k_gwriteW(float* __restrict__ out) {
    int gt = blockIdx.x * blockDim.x + threadIdx.x;
    int w = gt >> 5, lane = gt & 31;
    if (w >= NPT) return;
    int T = g.tot[5];
    int c = g.cid[w];
    int x = c & 63, y = (c >> 6) & 63, z = c >> 12;
    int n = 0, b = 0;
    if (lane < 27) {
        int nx = x + cNX[lane], ny = y + cNY[lane], nz = z + cNZ[lane];
        if ((unsigned)nx < 64u && (unsigned)ny < 64u && (unsigned)nz < 64u) {
            int cc = nx + (ny << 6) + (nz << 12);
            n = g.cnt0[cc];
            b = g.cstart0[cc];
        }
    }
    int off = wscan(n) - n;                 // exclusive, lane order = NEIG order
    int col = g.poff[w] + off;
    float fi = (float)w;
    for (int t = 0; t < n; t++) {
        out[col + t] = (float)g.order0[b + t];
        out[T + col + t] = fi;
    }
}

// ------------------------------------------------------------------ level 1 (64->32)
__global__ void k_l1occup() {
    int r = blockIdx.x * blockDim.x + threadIdx.x;
    if (r >= g.tot[0]) return;
    int e = g.neA[r];
    int cc = ((e & 63) >> 1) | ((((e >> 6) & 63) >> 1) << 5) | (((e >> 12) >> 1) << 10);
    atomicAdd(&g.cntLcell[cc], 1);
}

__global__ void k_l1sc() {
    int r = blockIdx.x * blockDim.x + threadIdx.x;
    if (r >= g.tot[0]) return;
    int e = g.neA[r];
    int cc = ((e & 63) >> 1) | ((((e >> 6) & 63) >> 1) << 5) | (((e >> 12) >> 1) << 10);
    g.segL[r] = g.rankL[cc];
    int slot = g.cstartLcell[cc] + atomicAdd(&g.curL[cc], 1);
    g.ordL[slot] = r;
}

__global__ void k_l1sort() {
    int s = blockIdx.x * blockDim.x + threadIdx.x;
    if (s >= g.tot[1]) return;
    int cc = g.neA[262144 + s];
    int n = g.cntLcell[cc];
    int b = g.cstartLcell[cc];
    g.cntR[s] = n;
    g.cstR[s] = b;
    if (n < 2) return;
    int* a = g.ordL + b;
    for (int i = 1; i < n; i++) {
        int v = a[i], j = i - 1;
        while (j >= 0 && a[j] > v) { a[j + 1] = a[j]; j--; }
        a[j + 1] = v;
    }
}

// ------------------------------------------------------------------ levels 2..4 single-block megakernel
template<int GL, int PGb>
__global__ void __launch_bounds__(1024) k_mega(const int* __restrict__ nePrev, int npIdx, int nIdx,
                                               int* __restrict__ rinfo, int* __restrict__ ne,
                                               int* __restrict__ seg, int* __restrict__ ord,
                                               int* __restrict__ cntR, int* __restrict__ cstR) {
    constexpr int GS = GL * GL * GL;
    constexpr int GLb = (GL == 16) ? 4 : (GL == 8) ? 3 : 2;
    constexpr int PG = 1 << PGb;
    __shared__ int sA[GS];
    __shared__ int sB[GS];
    __shared__ int mws[32], mwo[32], mtot;
    int tid = threadIdx.x;
    int np = g.tot[npIdx];
    for (int i = tid; i < GS; i += 1024) sA[i] = 0;
    __syncthreads();
    for (int r = tid; r < np; r += 1024) {
        int e = __ldg(nePrev + r);
        int c = ((e & (PG - 1)) >> 1) | ((((e >> PGb) & (PG - 1)) >> 1) << GLb)
              | (((e >> (2 * PGb)) >> 1) << (2 * GLb));
        atomicAdd(&sA[c], 1);
    }
    __syncthreads();
    int i0 = tid * 4;
    int p[4]; int tt = 0;
#pragma unroll
    for (int j = 0; j < 4; j++) {
        int q = 0, idx = i0 + j;
        if (idx < GS) { int cv = sA[idx]; q = cv | ((cv > 0) << 16); }
        p[j] = q; tt += q;
    }
    int inc = wscan(tt);
    if ((tid & 31) == 31) mws[tid >> 5] = inc;
    __syncthreads();
    if (tid == 0) {
        int s = 0;
        for (int w = 0; w < 32; w++) { int x = mws[w]; mwo[w] = s; s += x; }
        mtot = s;
    }
    __syncthreads();
    int exc = mwo[tid >> 5] + inc - tt;
#pragma unroll
    for (int j = 0; j < 4; j++) { int idx = i0 + j; if (idx < GS) sB[idx] = exc; exc += p[j]; }
    if (tid == 0) g.tot[nIdx] = mtot >> 16;
    __syncthreads();
    for (int c = tid; c < GS; c += 1024) {
        int cv = sA[c];
        int v = sB[c];
        int rk = v >> 16;
        rinfo[c] = cv ? rk + 1 : 0;
        if (cv) { ne[rk] = c; cntR[rk] = cv; cstR[rk] = v & 0xffff; }
    }
    __syncthreads();
    for (int r = tid; r < np; r += 1024) {
        int e = __ldg(nePrev + r);
        int c = ((e & (PG - 1)) >> 1) | ((((e >> PGb) & (PG - 1)) >> 1) << GLb)
              | (((e >> (2 * PGb)) >> 1) << (2 * GLb));
        int v = sB[c];
        seg[r] = v >> 16;
        int old = atomicAdd(&sA[c], 1 << 16);
        ord[(v & 0xffff) + (old >> 16)] = r;
    }
    __syncthreads();
    for (int c = tid; c < GS; c += 1024) {
        int ncnt = sA[c] & 0xffff;
        if (ncnt >= 2) {
            int* a = ord + (sB[c] & 0xffff);
            for (int i = 1; i < ncnt; i++) {
                int vv = a[i], j = i - 1;
                while (j >= 0 && a[j] > vv) { a[j + 1] = a[j]; j--; }
                a[j + 1] = vv;
            }
        }
    }
}

// ------------------------------------------------------------------ edges: per-(q,k) domain
template<int CG, int FL>
__global__ void k_ecnt27(const int* __restrict__ rinfo, int* __restrict__ ecnt) {
    int idx = blockIdx.x * 256 + threadIdx.x;
    if (idx >= CG * CG * CG * 27) return;
    int k = idx % 27, q = idx / 27;
    int qx = q % CG, qy = (q / CG) % CG, qz = q / (CG * CG);
    int nx = qx + cNX[k], ny = qy + cNY[k], nz = qz + cNZ[k];
    int c = 0;
    if ((unsigned)nx < (unsigned)CG && (unsigned)ny < (unsigned)CG && (unsigned)nz < (unsigned)CG) {
        const int2* rp = (const int2*)rinfo;
        int aa = 2 * qx + 2 * qy * FL + 2 * qz * FL * FL;
        int bb = 2 * nx + 2 * ny * FL + 2 * nz * FL * FL;
        int2 a01 = __ldg(rp + (aa >> 1));
        int2 a23 = __ldg(rp + ((aa + FL) >> 1));
        int2 a45 = __ldg(rp + ((aa + FL * FL) >> 1));
        int2 a67 = __ldg(rp + ((aa + FL * FL + FL) >> 1));
        int2 b01 = __ldg(rp + (bb >> 1));
        int2 b23 = __ldg(rp + ((bb + FL) >> 1));
        int2 b45 = __ldg(rp + ((bb + FL * FL) >> 1));
        int2 b67 = __ldg(rp + ((bb + FL * FL + FL) >> 1));
        int occB = (b01.x != 0) | ((b01.y != 0) << 1) | ((b23.x != 0) << 2) | ((b23.y != 0) << 3)
                 | ((b45.x != 0) << 4) | ((b45.y != 0) << 5) | ((b67.x != 0) << 6) | ((b67.y != 0) << 7);
        int av[8] = {a01.x, a01.y, a23.x, a23.y, a45.x, a45.y, a67.x, a67.y};
        const int* bm = g.bmask + (k << 3);
#pragma unroll
        for (int a = 0; a < 8; a++)
            if (av[a]) c += __popc(bm[a] & occB);
    }
    ecnt[idx] = c;
}

template<int CG, int FL>
__global__ void k_ewrite27(const int* __restrict__ rinfo, const int* __restrict__ eoff,
                           float* __restrict__ out) {
    int idx = blockIdx.x * 256 + threadIdx.x;
    if (idx >= CG * CG * CG * 27) return;
    int k = idx % 27, q = idx / 27;
    int qx = q % CG, qy = (q / CG) % CG, qz = q / (CG * CG);
    int nx = qx + cNX[k], ny = qy + cNY[k], nz = qz + cNZ[k];
    if (!((unsigned)nx < (unsigned)CG && (unsigned)ny < (unsigned)CG && (unsigned)nz < (unsigned)CG))
        return;
    const int2* rp = (const int2*)rinfo;
    int aa = 2 * qx + 2 * qy * FL + 2 * qz * FL * FL;
    int bb = 2 * nx + 2 * ny * FL + 2 * nz * FL * FL;
    int2 a01 = __ldg(rp + (aa >> 1));
    int2 a23 = __ldg(rp + ((aa + FL) >> 1));
    int2 a45 = __ldg(rp + ((aa + FL * FL) >> 1));
    int2 a67 = __ldg(rp + ((aa + FL * FL + FL) >> 1));
    int2 b01 = __ldg(rp + (bb >> 1));
    int2 b23 = __ldg(rp + ((bb + FL) >> 1));
    int2 b45 = __ldg(rp + ((bb + FL * FL) >> 1));
    int2 b67 = __ldg(rp + ((bb + FL * FL + FL) >> 1));
    int occB = (b01.x != 0) | ((b01.y != 0) << 1) | ((b23.x != 0) << 2) | ((b23.y != 0) << 3)
             | ((b45.x != 0) << 4) | ((b45.y != 0) << 5) | ((b67.x != 0) << 6) | ((b67.y != 0) << 7);
    int av[8] = {a01.x, a01.y, a23.x, a23.y, a45.x, a45.y, a67.x, a67.y};
    int rv[8] = {b01.x, b01.y, b23.x, b23.y, b45.x, b45.y, b67.x, b67.y};
    int E = g.E;
    float* o0 = out + g.oedge + __ldg(eoff + idx);
#pragma unroll
    for (int a = 0; a < 8; a++) {
        if (av[a]) {
            float ra = (float)(av[a] - 1);
            int m = g.bmask[(k << 3) | a] & occB;
            while (m) {
                int b = __ffs(m) - 1;
                m &= m - 1;
                o0[0] = (float)(rv[b] - 1);
                o0[E] = ra;
                o0++;
            }
        }
    }
}

// ------------------------------------------------------------------ sv (atomic-free)
__global__ void k_sv0seg(const float* __restrict__ nodes) {
    int r = blockIdx.x * blockDim.x + threadIdx.x;
    if (r >= g.tot[0]) return;
    int c = g.neA[r];
    int n = g.cnt0[c];
    int b = g.cstart0[c];
    float acc[10];
#pragma unroll
    for (int j = 0; j < 10; j++) acc[j] = 0.f;
    for (int t = 0; t < n; t++) {
        int i = g.order0[b + t];
        const float* row = nodes + (size_t)i * 10;
        float m = row[0];
        acc[0] += m;
#pragma unroll
        for (int j = 1; j < 10; j++) acc[j] += m * row[j];
    }
    float* o = g_svraw + (size_t)r * 10;
#pragma unroll
    for (int j = 0; j < 10; j++) o[j] = acc[j];
}

__global__ void k_svaggseg(int prevBase, int curBase, const int* __restrict__ ord,
                           const int* __restrict__ cntR, const int* __restrict__ cstR, int totIdx) {
    int s = blockIdx.x * blockDim.x + threadIdx.x;
    if (s >= g.tot[totIdx]) return;
    int n = cntR[s];
    int b = cstR[s];
    float acc[10];
#pragma unroll
    for (int j = 0; j < 10; j++) acc[j] = 0.f;
    for (int t = 0; t < n; t++) {
        const float* row = g_svraw + (size_t)(prevBase + ord[b + t]) * 10;
#pragma unroll
        for (int j = 0; j < 10; j++) acc[j] += row[j];
    }
    float* o = g_svraw + (size_t)(curBase + s) * 10;
#pragma unroll
    for (int j = 0; j < 10; j++) o[j] = acc[j];
}

// ------------------------------------------------------------------ layout + writers
__global__ void k_off() {
    int n0 = g.tot[0], n1 = g.tot[1], n2 = g.tot[2], n3 = g.tot[3], n4 = g.tot[4];
    int T = g.tot[5], E = g.tot[6];
    int A = NPT + n0 + n1 + n2 + n3;
    int S = n0 + n1 + n2 + n3 + n4;
    g.A = A; g.S = S; g.E = E;
    g.oassign = 2 * T;
    g.osv = 2 * T + 2 * A;
    g.oedge = g.osv + 10 * S;
    g.oids = g.oedge + 2 * E;
    g.svb[0] = 0; g.svb[1] = n0; g.svb[2] = n0 + n1; g.svb[3] = n0 + n1 + n2; g.svb[4] = n0 + n1 + n2 + n3;
    g.ab[0] = 0; g.ab[1] = NPT; g.ab[2] = NPT + n0; g.ab[3] = NPT + n0 + n1; g.ab[4] = NPT + n0 + n1 + n2;
}

__global__ void k_awriteAll(float* __restrict__ out) {
    int t = blockIdx.x * blockDim.x + threadIdx.x;
    if (t >= g.A) return;
    const int* ord; const int* seg; int loc;
    if (t < g.ab[1])      { ord = g.order0;          seg = g.seg0;            loc = t; }
    else if (t < g.ab[2]) { ord = g.ordL + 0;        seg = g.segL + 0;        loc = t - g.ab[1]; }
    else if (t < g.ab[3]) { ord = g.ordL + 262144;   seg = g.segL + 262144;   loc = t - g.ab[2]; }
    else if (t < g.ab[4]) { ord = g.ordL + 294912;   seg = g.segL + 294912;   loc = t - g.ab[3]; }
    else                  { ord = g.ordL + 299008;   seg = g.segL + 299008;   loc = t - g.ab[4]; }
    int p = ord[loc];
    out[g.oassign + t] = (float)seg[p];
    out[g.oassign + g.A + t] = (float)p;
}

__global__ void k_svidwrite(float* __restrict__ out) {
    int r = blockIdx.x * blockDim.x + threadIdx.x;
    if (r >= g.S) return;
    int neo;
    if (r < g.svb[1])      neo = 0;
    else if (r < g.svb[2]) neo = 262144 - g.svb[1];
    else if (r < g.svb[3]) neo = 294912 - g.svb[2];
    else if (r < g.svb[4]) neo = 299008 - g.svb[3];
    else                   neo = 299520 - g.svb[4];
    int loc = neo + r;
    out[g.oids + r] = (float)g.neA[loc];
    const float* raw = g_svraw + (size_t)loc * 10;
    float m = raw[0];
    float* o = out + g.osv + (size_t)r * 10;
    o[0] = m;
#pragma unroll
    for (int j = 1; j < 10; j++) o[j] = raw[j] / m;
}

// ------------------------------------------------------------------ host
extern "C" void kernel_launch(void* const* d_in, const int* in_sizes, int n_in,
                              void* d_out, int out_size) {
    const float* nodes = (const float*)d_in[0];
    float* out = (float*)d_out;
    GG* G;
    cudaGetSymbolAddress((void**)&G, g);
    int *rinfo0, *rinfoL, *ecnt8, *eoff8, *tmpc;
    cudaGetSymbolAddress((void**)&rinfo0, g_rinfo0);
    cudaGetSymbolAddress((void**)&rinfoL, g_rinfoL);
    cudaGetSymbolAddress((void**)&ecnt8, g_ecnt8);
    cudaGetSymbolAddress((void**)&eoff8, g_eoff8);
    cudaGetSymbolAddress((void**)&tmpc, g_tmpc);

    const int EOFF[5] = {0, 884736, 995328, 1009152, 1010880};
    const int ETOT = 1011096;

    cudaMemsetAsync(G, 0, offsetof(GG, zend), 0);
    k_foldpre<<<768, 256>>>(nodes);
    k_fold3b<<<1, 128>>>(nodes);
    k_cells<<<1024, 256>>>(nodes);
    k_scanOcc<<<32, 512>>>(G->cnt0, G->rank0, G->cstart0, rinfo0, G->neA, C0, &G->tot[0], 0, 0);
    k_init2<<<1, 256>>>();
    // per-cell degree via separable 3x3x3 box filter: cnt0 -> tmpc -> eoff8(tmp) -> ecnt8(deg)
    k_conv<<<1024, 256>>>(G->cnt0, tmpc, 0);
    k_conv<<<1024, 256>>>(tmpc, eoff8, 6);
    k_conv<<<1024, 256>>>(eoff8, ecnt8, 12);
    k_scatseg<<<1024, 256>>>();
    k_sort0<<<1024, 256>>>();
    k_scan1<<<32, 512>>>(G->pdeg, G->poff, NPT, &G->tot[5], 1, 32);

    // level 1
    k_l1occup<<<1024, 256>>>();
    k_scanOcc<<<4, 512>>>(G->cntLcell, G->rankL, G->cstartLcell, rinfoL, G->neA + 262144,
                          32768, &G->tot[1], 4, 64);
    k_l1sc<<<1024, 256>>>();
    k_l1sort<<<128, 256>>>();

    // levels 2..4
    k_mega<16, 5><<<1, 1024>>>(G->neA + 262144, 1, 2, rinfoL + 32768, G->neA + 294912,
                               G->segL + 262144, G->ordL + 262144, G->cntR + 32768, G->cstR + 32768);
    k_mega<8, 4><<<1, 1024>>>(G->neA + 294912, 2, 3, rinfoL + 36864, G->neA + 299008,
                              G->segL + 294912, G->ordL + 294912, G->cntR + 36864, G->cstR + 36864);
    k_mega<4, 3><<<1, 1024>>>(G->neA + 299008, 3, 4, rinfoL + 37376, G->neA + 299520,
                              G->segL + 299008, G->ordL + 299008, G->cntR + 37376, G->cstR + 37376);

    // edges
    k_ecnt27<32, 64><<<3456, 256>>>(rinfo0,        ecnt8 + EOFF[0]);
    k_ecnt27<16, 32><<<432, 256>>>(rinfoL,         ecnt8 + EOFF[1]);
    k_ecnt27<8, 16><<<54, 256>>>(rinfoL + 32768,   ecnt8 + EOFF[2]);
    k_ecnt27<4, 8><<<7, 256>>>(rinfoL + 36864,     ecnt8 + EOFF[3]);
    k_ecnt27<2, 4><<<1, 256>>>(rinfoL + 37376,     ecnt8 + EOFF[4]);
    k_scan1<<<(ETOT + 8191) / 8192, 512>>>(ecnt8, eoff8, ETOT, &G->tot[6], 2, 128);

    k_off<<<1, 1>>>();

    // supervoxel features
    k_sv0seg<<<1024, 256>>>(nodes);
    k_svaggseg<<<128, 256>>>(0,      262144, G->ordL + 0,      G->cntR + 0,     G->cstR + 0,     1);
    k_svaggseg<<<16, 256>>>(262144, 294912, G->ordL + 262144, G->cntR + 32768, G->cstR + 32768, 2);
    k_svaggseg<<<2, 256>>>(294912, 299008, G->ordL + 294912, G->cntR + 36864, G->cstR + 36864, 3);
    k_svaggseg<<<1, 256>>>(299008, 299520, G->ordL + 299008, G->cntR + 37376, G->cstR + 37376, 4);

    // writers
    k_gwriteW<<<32768, 256>>>(out);
    k_awriteAll<<<(NPT + 299520 + 255) / 256, 256>>>(out);
    k_svidwrite<<<1170, 256>>>(out);
    k_ewrite27<32, 64><<<3456, 256>>>(rinfo0,      eoff8 + EOFF[0], out);
    k_ewrite27<16, 32><<<432, 256>>>(rinfoL,       eoff8 + EOFF[1], out);
    k_ewrite27<8, 16><<<54, 256>>>(rinfoL + 32768, eoff8 + EOFF[2], out);
    k_ewrite27<4, 8><<<7, 256>>>(rinfoL + 36864,   eoff8 + EOFF[3], out);
    k_ewrite27<2, 4><<<1, 256>>>(rinfoL + 37376,   eoff8 + EOFF[4], out);
    (void)in_sizes; (void)n_in; (void)out_size;
}

// round 16
// speedup vs baseline: 1.3695x; 1.2824x over previous
#include <cuda_runtime.h>
#include <cstdint>
#include <cstddef>

#define NPT 262144
#define C0  262144
#define FULLM 0xffffffffu
typedef unsigned long long ull;

__constant__ int cNX[27] = {-1,0,1,-1,0,1,-1,0,1,-1,0,1,-1,0,1,-1,0,1,-1,0,1,-1,0,1,-1,0,1};
__constant__ int cNY[27] = {-1,-1,-1,0,0,0,1,1,1,-1,-1,-1,0,0,0,1,1,1,-1,-1,-1,0,0,0,1,1,1};
__constant__ int cNZ[27] = {-1,-1,-1,-1,-1,-1,-1,-1,-1,0,0,0,0,0,0,0,0,0,1,1,1,1,1,1,1,1,1};

struct __align__(256) GG {
    // ---------- zero block (memset each launch) ----------
    int   occ0[C0];
    int   cnt0[C0];
    int   cur0[C0];
    int   occL[32768];
    int   cntL[32768];
    int   curL[32768];
    float svraw[299584 * 10];
    int   tick[16];
    ull   scanflags[2304];
    int   tot[16];          // 0..4 = n_l, 5 = T, 6 = E
    int   zend[4];
    // ---------- rest ----------
    int   cid[NPT];
    int   rank0[C0];
    int   cstart0[C0];
    int   order0[NPT];
    int   seg0[NPT];
    int   pdeg[NPT];
    int   poff[NPT];
    int   neA[299584];
    int   rankL[32768];
    int   cstartL[32768];
    int   segL[299520];
    int   ordL[299520];
    int   bmask[216];
    int   Stab[3 * 128 * 6];
    int   Ttab[3 * 128 * 6];
    int   mnb[4], mxb[4];
    float bnd[3 * 63];
    int oassign, osv, oedge, oids, A, S, E;
    int svb[5], ab[5];
};
__device__ GG g;

__device__ __align__(16) int g_rinfo0[C0];
__device__ __align__(16) int g_rinfoL[37440];
__device__ __align__(16) int g_ecnt8[8088768];
__device__ __align__(16) int g_eoff8[8088768];

// ------------------------------------------------------------------ scan utils
__device__ __forceinline__ int wscan(int x) {
    int lane = threadIdx.x & 31;
#pragma unroll
    for (int d = 1; d < 32; d <<= 1) {
        int y = __shfl_up_sync(FULLM, x, d);
        if (lane >= d) x += y;
    }
    return x;
}
__device__ __forceinline__ ull wscan64(ull x) {
    int lane = threadIdx.x & 31;
#pragma unroll
    for (int d = 1; d < 32; d <<= 1) {
        ull y = __shfl_up_sync(FULLM, x, d);
        if (lane >= d) x += y;
    }
    return x;
}

// single-array scan: 512 thr x 16 items, warp-parallel lookback
__global__ void __launch_bounds__(512) k_scan1(const int* __restrict__ in, int* __restrict__ out,
                                               int n, int* tot, int ti, int fo) {
    __shared__ int sbid, sexc;
    __shared__ int wsum[16], woff[16];
    int tid = threadIdx.x;
    if (tid == 0) sbid = atomicAdd(&g.tick[ti], 1);
    __syncthreads();
    int bid = sbid;
    int base = bid * 8192 + tid * 16;
    int v[16]; int t = 0;
    if (base + 16 <= n) {
        const int4* p = (const int4*)(in + base);
#pragma unroll
        for (int j = 0; j < 4; j++) {
            int4 x = __ldg(p + j);
            v[4*j] = x.x; v[4*j+1] = x.y; v[4*j+2] = x.z; v[4*j+3] = x.w;
        }
    } else {
#pragma unroll
        for (int j = 0; j < 16; j++) v[j] = (base + j < n) ? in[base + j] : 0;
    }
#pragma unroll
    for (int j = 0; j < 16; j++) t += v[j];
    int inc = wscan(t);
    if ((tid & 31) == 31) wsum[tid >> 5] = inc;
    __syncthreads();
    if (tid < 32) {
        int x = (tid < 16) ? wsum[tid] : 0;
        int iw = wscan(x);
        if (tid < 16) woff[tid] = iw - x;
        int B = __shfl_sync(FULLM, iw, 15);
        ull* fl = g.scanflags + fo;
        int exc = 0;
        if (bid == 0) {
            if (tid == 0) atomicExch(&fl[0], (2ULL << 62) | (unsigned)B);
        } else {
            if (tid == 0) atomicExch(&fl[bid], (1ULL << 62) | (unsigned)B);
            int lb = bid - 1;
            while (true) {
                int idx = lb - tid;
                ull w = 0; int st = 2;
                if (idx >= 0) {
                    do { w = atomicAdd(&fl[idx], 0ULL); } while (!(w >> 62));
                    st = (int)(w >> 62);
                }
                unsigned pm = __ballot_sync(FULLM, st == 2);
                int val = (int)(unsigned)w;
                int firstP = pm ? (__ffs(pm) - 1) : 32;
                if (tid > firstP) val = 0;
#pragma unroll
                for (int d = 16; d >= 1; d >>= 1) val += __shfl_xor_sync(FULLM, val, d);
                exc += val;
                if (pm) break;
                lb -= 32;
            }
            if (tid == 0) atomicExch(&fl[bid], (2ULL << 62) | (unsigned)(exc + B));
        }
        if (tid == 0) { sexc = exc; if (tot && bid == (int)gridDim.x - 1) *tot = exc + B; }
    }
    __syncthreads();
    int off = sexc + woff[tid >> 5] + inc - t;
    if (base + 16 <= n) {
        int4* q = (int4*)(out + base);
#pragma unroll
        for (int j = 0; j < 4; j++) {
            int4 x;
            x.x = off; off += v[4*j];
            x.y = off; off += v[4*j+1];
            x.z = off; off += v[4*j+2];
            x.w = off; off += v[4*j+3];
            q[j] = x;
        }
    } else {
        for (int j = 0; j < 16; j++) { if (base + j < n) out[base + j] = off; off += v[j]; }
    }
}

// dual-array scan (packed 28-bit fields)
#define M28 ((1ULL << 28) - 1)
__global__ void __launch_bounds__(512) k_scan2(const int* __restrict__ in1, const int* __restrict__ in2,
                                               int* __restrict__ out1, int* __restrict__ out2,
                                               int n, int* tot1, int ti, int fo) {
    __shared__ int sbid;
    __shared__ ull sexc2;
    __shared__ ull wsum[16], woff[16];
    int tid = threadIdx.x;
    if (tid == 0) sbid = atomicAdd(&g.tick[ti], 1);
    __syncthreads();
    int bid = sbid;
    int base = bid * 8192 + tid * 16;
    ull v[16]; ull t = 0;
#pragma unroll
    for (int j = 0; j < 16; j++) {
        ull x = 0;
        if (base + j < n) x = (ull)(unsigned)in1[base + j] | ((ull)(unsigned)in2[base + j] << 28);
        v[j] = x; t += x;
    }
    ull inc = wscan64(t);
    if ((tid & 31) == 31) wsum[tid >> 5] = inc;
    __syncthreads();
    if (tid < 32) {
        ull x = (tid < 16) ? wsum[tid] : 0;
        ull iw = wscan64(x);
        if (tid < 16) woff[tid] = iw - x;
        ull B = __shfl_sync(FULLM, iw, 15);
        ull* fl = g.scanflags + fo;
        ull exc = 0;
        if (bid == 0) {
            if (tid == 0) atomicExch(&fl[0], (2ULL << 62) | B);
        } else {
            if (tid == 0) atomicExch(&fl[bid], (1ULL << 62) | B);
            int lb = bid - 1;
            while (true) {
                int idx = lb - tid;
                ull w = 0; int st = 2;
                if (idx >= 0) {
                    do { w = atomicAdd(&fl[idx], 0ULL); } while (!(w >> 62));
                    st = (int)(w >> 62);
                }
                unsigned pm = __ballot_sync(FULLM, st == 2);
                ull val = w & ((1ULL << 56) - 1);
                int firstP = pm ? (__ffs(pm) - 1) : 32;
                if (tid > firstP) val = 0;
#pragma unroll
                for (int d = 16; d >= 1; d >>= 1) val += __shfl_xor_sync(FULLM, val, d);
                exc += val;
                if (pm) break;
                lb -= 32;
            }
            if (tid == 0) atomicExch(&fl[bid], (2ULL << 62) | (exc + B));
        }
        if (tid == 0) { sexc2 = exc; if (tot1 && bid == (int)gridDim.x - 1) *tot1 = (int)((exc + B) & M28); }
    }
    __syncthreads();
    ull off = sexc2 + woff[tid >> 5] + inc - t;
#pragma unroll
    for (int j = 0; j < 16; j++) {
        if (base + j < n) { out1[base + j] = (int)(off & M28); out2[base + j] = (int)((off >> 28) & M28); }
        off += v[j];
    }
}

// ------------------------------------------------------------------ stage A
__global__ void k_init2() {
    int t = threadIdx.x;
    if (t < 3) { g.mnb[t] = 0x7f7fffff; g.mxb[t] = 0; }
    if (t < 216) {
        int k = t >> 3, a = t & 7;
        int ox = cNX[k], oy = cNY[k], oz = cNZ[k];
        int ax = a & 1, ay = (a >> 1) & 1, az = a >> 2;
        int m = 0;
        for (int b = 0; b < 8; b++) {
            int dx = 2 * ox + (b & 1) - ax;
            int dy = 2 * oy + ((b >> 1) & 1) - ay;
            int dz = 2 * oz + (b >> 2) - az;
            if (dx > 1 || dx < -1 || dy > 1 || dy < -1 || dz > 1 || dz < -1) m |= 1 << b;
        }
        g.bmask[t] = m;
    }
}

__global__ void __launch_bounds__(256) k_foldpre(const float* __restrict__ nodes) {
    int blk = blockIdx.x;             // 768 = c*6 + kk
    int c = blk / 6, kk = blk % 6, kb = kk + 12;
    float scale = __int_as_float((23 - kb + 127) << 23);
    int t = threadIdx.x;
    int s0 = 0, s1 = 0, s2 = 0, tie = 0;
    for (int e = t; e < 2048; e += 256) {
        const float* p = nodes + ((size_t)c * 2048 + e) * 10 + 4;
        float v0 = __fmul_rn(__ldg(p + 0), scale);
        float v1 = __fmul_rn(__ldg(p + 1), scale);
        float v2 = __fmul_rn(__ldg(p + 2), scale);
        int q0 = __float2int_rn(v0), q1 = __float2int_rn(v1), q2 = __float2int_rn(v2);
        if (fabsf(__fsub_rn(v0, (float)q0)) == 0.5f) tie = 1;
        if (fabsf(__fsub_rn(v1, (float)q1)) == 0.5f) tie = 1;
        if (fabsf(__fsub_rn(v2, (float)q2)) == 0.5f) tie = 1;
        s0 += q0; s1 += q1; s2 += q2;
    }
    s0 = __reduce_add_sync(FULLM, s0);
    s1 = __reduce_add_sync(FULLM, s1);
    s2 = __reduce_add_sync(FULLM, s2);
    tie = __any_sync(FULLM, tie);
    __shared__ int sh[8][4];
    int wid = t >> 5;
    if ((t & 31) == 0) { sh[wid][0] = s0; sh[wid][1] = s1; sh[wid][2] = s2; sh[wid][3] = tie; }
    __syncthreads();
    if (t == 0) {
        int a0 = 0, a1 = 0, a2 = 0, tt = 0;
        for (int w = 0; w < 8; w++) { a0 += sh[w][0]; a1 += sh[w][1]; a2 += sh[w][2]; tt |= sh[w][3]; }
        g.Stab[(0 * 128 + c) * 6 + kk] = a0;
        g.Stab[(1 * 128 + c) * 6 + kk] = a1;
        g.Stab[(2 * 128 + c) * 6 + kk] = a2;
        g.Ttab[(0 * 128 + c) * 6 + kk] = tt;
        g.Ttab[(1 * 128 + c) * 6 + kk] = tt;
        g.Ttab[(2 * 128 + c) * 6 + kk] = tt;
    }
}

__global__ void k_mmx(const float* __restrict__ nodes) {
    int t = blockIdx.x * blockDim.x + threadIdx.x;
    int i0 = t * 64;
    if (i0 >= NPT) return;
    int mn[3] = {0x7f7fffff, 0x7f7fffff, 0x7f7fffff};
    int mx[3] = {0, 0, 0};
    for (int i = i0; i < i0 + 64; i++) {
#pragma unroll
        for (int d = 0; d < 3; d++) {
            int b = __float_as_int(nodes[i * 10 + 4 + d]);
            mn[d] = min(mn[d], b);
            mx[d] = max(mx[d], b);
        }
    }
#pragma unroll
    for (int d = 0; d < 3; d++) {
        atomicMin(&g.mnb[d], mn[d]);
        atomicMax(&g.mxb[d], mx[d]);
    }
}

__global__ void k_fold3b(const float* __restrict__ nodes) {
    __shared__ float sref[3];
    int tid = threadIdx.x;
    if ((tid & 31) == 0 && tid < 96) {
        int d = tid >> 5;
        float s = 0.f;
        for (int c = 0; c < 128; c++) {
            int kb = (__float_as_int(s) >> 23) - 127;
            bool ok = false;
            float cand = 0.f;
            if (s > 0.f && kb >= 12 && kb <= 17) {
                int idx = (d * 128 + c) * 6 + (kb - 12);
                int S = g.Stab[idx];
                int tie = g.Ttab[idx];
                float u = __int_as_float((kb - 23 + 127) << 23);
                cand = __fadd_rn(s, __fmul_rn((float)S, u));
                float lim = __int_as_float((kb + 1 + 127) << 23);
                if (!tie && __fadd_rn(cand, 4.0f) < lim) ok = true;
            }
            if (ok) {
                s = cand;
            } else {
                const float* p = nodes + (size_t)c * 2048 * 10 + 4 + d;
#pragma unroll 8
                for (int e = 0; e < 2048; e++)
                    s = __fadd_rn(s, __ldg(p + e * 10));
            }
        }
        sref[d] = s * (1.0f / 262144.0f);
    }
    __syncthreads();
    float d0 = __fsub_rn(__int_as_float(g.mxb[0]), __int_as_float(g.mnb[0]));
    float d1 = __fsub_rn(__int_as_float(g.mxb[1]), __int_as_float(g.mnb[1]));
    float d2 = __fsub_rn(__int_as_float(g.mxb[2]), __int_as_float(g.mnb[2]));
    float box = fmaxf(d0, fmaxf(d1, d2));
    double half = (double)box * 0.5;
    float hf = (float)half;
    for (int t = tid; t < 189; t += 128) {
        int d = t / 63, i = t % 63 + 1;
        float r = sref[d];
        float start = __fsub_rn(r, hf);
        float stop  = __fadd_rn(r, hf);
        float delta = __fsub_rn(stop, start);
        float step  = __fmul_rn(delta, 1.0f / 64.0f);
        float b = __fadd_rn(__fmul_rn((float)i, step), start);
        g.bnd[d * 63 + (i - 1)] = b;
    }
}

__device__ __forceinline__ int ub63(const float* __restrict__ b, float v) {
    int lo = 0, hi = 63;
    while (lo < hi) {
        int m = (lo + hi) >> 1;
        if (b[m] <= v) lo = m + 1; else hi = m;
    }
    return lo;
}

__global__ void k_cells(const float* __restrict__ nodes) {
    int i = blockIdx.x * blockDim.x + threadIdx.x;
    if (i >= NPT) return;
    float x = nodes[i * 10 + 4], y = nodes[i * 10 + 5], z = nodes[i * 10 + 6];
    int xg = ub63(g.bnd, x);
    int yg = 63 - ub63(g.bnd + 63, y);
    int zg = 63 - ub63(g.bnd + 126, z);
    int c = xg + (yg << 6) + (zg << 12);
    g.cid[i] = c;
    g.occ0[c] = 1;
    atomicAdd(&g.cnt0[c], 1);
}

__global__ void k_post0() {
    int c = blockIdx.x * blockDim.x + threadIdx.x;
    if (c >= C0) return;
    int o = g.occ0[c];
    int r = g.rank0[c];
    g_rinfo0[c] = o ? r + 1 : 0;
    if (o) g.neA[r] = c;
}

__global__ void k_scatseg() {
    int i = blockIdx.x * blockDim.x + threadIdx.x;
    if (i >= NPT) return;
    int c = g.cid[i];
    int slot = g.cstart0[c] + atomicAdd(&g.cur0[c], 1);
    g.order0[slot] = i;
    g.seg0[i] = g.rank0[c];
    int x = c & 63, y = (c >> 6) & 63, z = c >> 12;
    int d = 0;
#pragma unroll
    for (int k = 0; k < 27; k++) {
        int nx = x + cNX[k], ny = y + cNY[k], nz = z + cNZ[k];
        if ((unsigned)nx < 64u && (unsigned)ny < 64u && (unsigned)nz < 64u)
            d += g.cnt0[nx + (ny << 6) + (nz << 12)];
    }
    g.pdeg[i] = d;
}

// register-staged insertion sort (runs are tiny; global fallback for safety)
__global__ void k_sort0() {
    int c = blockIdx.x * blockDim.x + threadIdx.x;
    if (c >= C0) return;
    int n = g.cnt0[c];
    if (n < 2) return;
    int* a = g.order0 + g.cstart0[c];
    if (n <= 32) {
        int buf[32];
        for (int i = 0; i < n; i++) buf[i] = a[i];
        for (int i = 1; i < n; i++) {
            int v = buf[i], j = i - 1;
            while (j >= 0 && buf[j] > v) { buf[j + 1] = buf[j]; j--; }
            buf[j + 1] = v;
        }
        for (int i = 0; i < n; i++) a[i] = buf[i];
    } else {
        for (int i = 1; i < n; i++) {
            int v = a[i], j = i - 1;
            while (j >= 0 && a[j] > v) { a[j + 1] = a[j]; j--; }
            a[j + 1] = v;
        }
    }
}

__global__ void k_gwrite(float* __restrict__ out) {
    int i = blockIdx.x * blockDim.x + threadIdx.x;
    if (i >= NPT) return;
    int T = g.tot[5];
    int c = g.cid[i];
    int x = c & 63, y = (c >> 6) & 63, z = c >> 12;
    int col = g.poff[i];
    float fi = (float)i;
    for (int k = 0; k < 27; k++) {
        int nx = x + cNX[k], ny = y + cNY[k], nz = z + cNZ[k];
        if ((unsigned)nx < 64u && (unsigned)ny < 64u && (unsigned)nz < 64u) {
            int cc = nx + (ny << 6) + (nz << 12);
            int n = g.cnt0[cc];
            if (n) {
                int b = g.cstart0[cc];
                for (int t = 0; t < n; t++) {
                    out[col] = (float)g.order0[b + t];
                    out[T + col] = fi;
                    col++;
                }
            }
        }
    }
}

// ------------------------------------------------------------------ level 1 (64->32)
__global__ void k_l1occup() {
    int r = blockIdx.x * blockDim.x + threadIdx.x;
    if (r >= g.tot[0]) return;
    int e = g.neA[r];
    g.occL[((e & 63) >> 1) | ((((e >> 6) & 63) >> 1) << 5) | (((e >> 12) >> 1) << 10)] = 1;
}

__global__ void k_l1post() {
    int c = blockIdx.x * blockDim.x + threadIdx.x;
    if (c >= 32768) return;
    int o = g.occL[c];
    int r = g.rankL[c];
    g_rinfoL[c] = o ? r + 1 : 0;
    if (o) g.neA[262144 + r] = c;
}

__global__ void k_l1seg() {
    int r = blockIdx.x * blockDim.x + threadIdx.x;
    if (r >= g.tot[0]) return;
    int e = g.neA[r];
    int s = g.rankL[((e & 63) >> 1) | ((((e >> 6) & 63) >> 1) << 5) | (((e >> 12) >> 1) << 10)];
    g.segL[r] = s;
    atomicAdd(&g.cntL[s], 1);
}

__global__ void k_l1scat() {
    int r = blockIdx.x * blockDim.x + threadIdx.x;
    if (r >= g.tot[0]) return;
    int s = g.segL[r];
    g.ordL[g.cstartL[s] + atomicAdd(&g.curL[s], 1)] = r;
}

__global__ void k_l1sort() {
    int s = blockIdx.x * blockDim.x + threadIdx.x;
    if (s >= g.tot[1]) return;
    int n = g.cntL[s];
    if (n < 2) return;
    int* a = g.ordL + g.cstartL[s];
    if (n <= 32) {
        int buf[32];
        for (int i = 0; i < n; i++) buf[i] = a[i];
        for (int i = 1; i < n; i++) {
            int v = buf[i], j = i - 1;
            while (j >= 0 && buf[j] > v) { buf[j + 1] = buf[j]; j--; }
            buf[j + 1] = v;
        }
        for (int i = 0; i < n; i++) a[i] = buf[i];
    } else {
        for (int i = 1; i < n; i++) {
            int v = a[i], j = i - 1;
            while (j >= 0 && a[j] > v) { a[j + 1] = a[j]; j--; }
            a[j + 1] = v;
        }
    }
}

// ------------------------------------------------------------------ levels 2..4 single-block megakernel
template<int GL, int PGb>
__global__ void __launch_bounds__(1024) k_mega(const int* __restrict__ nePrev, int npIdx, int nIdx,
                                               int* __restrict__ rinfo, int* __restrict__ ne,
                                               int* __restrict__ seg, int* __restrict__ ord) {
    constexpr int GS = GL * GL * GL;
    constexpr int GLb = (GL == 16) ? 4 : (GL == 8) ? 3 : 2;
    constexpr int PG = 1 << PGb;
    __shared__ int sA[GS];
    __shared__ int sB[GS];
    __shared__ int mws[32], mwo[32], mtot;
    int tid = threadIdx.x;
    int np = g.tot[npIdx];
    for (int i = tid; i < GS; i += 1024) sA[i] = 0;
    __syncthreads();
    for (int r = tid; r < np; r += 1024) {
        int e = __ldg(nePrev + r);
        int c = ((e & (PG - 1)) >> 1) | ((((e >> PGb) & (PG - 1)) >> 1) << GLb)
              | (((e >> (2 * PGb)) >> 1) << (2 * GLb));
        atomicAdd(&sA[c], 1);
    }
    __syncthreads();
    int i0 = tid * 4;
    int p[4]; int tt = 0;
#pragma unroll
    for (int j = 0; j < 4; j++) {
        int q = 0, idx = i0 + j;
        if (idx < GS) { int cv = sA[idx]; q = cv | ((cv > 0) << 16); }
        p[j] = q; tt += q;
    }
    int inc = wscan(tt);
    if ((tid & 31) == 31) mws[tid >> 5] = inc;
    __syncthreads();
    if (tid == 0) {
        int s = 0;
        for (int w = 0; w < 32; w++) { int x = mws[w]; mwo[w] = s; s += x; }
        mtot = s;
    }
    __syncthreads();
    int exc = mwo[tid >> 5] + inc - tt;
#pragma unroll
    for (int j = 0; j < 4; j++) { int idx = i0 + j; if (idx < GS) sB[idx] = exc; exc += p[j]; }
    if (tid == 0) g.tot[nIdx] = mtot >> 16;
    __syncthreads();
    for (int c = tid; c < GS; c += 1024) {
        int cv = sA[c];
        int rk = sB[c] >> 16;
        rinfo[c] = cv ? rk + 1 : 0;
        if (cv) ne[rk] = c;
    }
    __syncthreads();
    for (int r = tid; r < np; r += 1024) {
        int e = __ldg(nePrev + r);
        int c = ((e & (PG - 1)) >> 1) | ((((e >> PGb) & (PG - 1)) >> 1) << GLb)
              | (((e >> (2 * PGb)) >> 1) << (2 * GLb));
        int v = sB[c];
        seg[r] = v >> 16;
        int old = atomicAdd(&sA[c], 1 << 16);
        ord[(v & 0xffff) + (old >> 16)] = r;
    }
    __syncthreads();
    for (int c = tid; c < GS; c += 1024) {
        int ncnt = sA[c] & 0xffff;
        if (ncnt >= 2) {
            int* a = ord + (sB[c] & 0xffff);
            for (int i = 1; i < ncnt; i++) {
                int vv = a[i], j = i - 1;
                while (j >= 0 && a[j] > vv) { a[j + 1] = a[j]; j--; }
                a[j + 1] = vv;
            }
        }
    }
}

// ------------------------------------------------------------------ edges (all 5 levels, one domain)
__device__ __forceinline__ void edgeDecode(int idx, int& local, int& CGb, const int*& rinfo) {
    if (idx < 7077888)      { local = idx;           CGb = 5; rinfo = g_rinfo0; }
    else if (idx < 7962624) { local = idx - 7077888; CGb = 4; rinfo = g_rinfoL; }
    else if (idx < 8073216) { local = idx - 7962624; CGb = 3; rinfo = g_rinfoL + 32768; }
    else if (idx < 8087040) { local = idx - 8073216; CGb = 2; rinfo = g_rinfoL + 36864; }
    else                    { local = idx - 8087040; CGb = 1; rinfo = g_rinfoL + 37376; }
}

__global__ void k_ecntAll(int* __restrict__ ecnt) {
    int idx = blockIdx.x * 256 + threadIdx.x;
    if (idx >= 8088768) return;
    int local, CGb; const int* rinfo;
    edgeDecode(idx, local, CGb, rinfo);
    int CG = 1 << CGb, FLb = CGb + 1, FL = 1 << FLb, FLsq = 1 << (2 * FLb);
    int a = local & 7, qk = local >> 3;
    int k = qk % 27, q = qk / 27;
    int qx = q & (CG - 1), qy = (q >> CGb) & (CG - 1), qz = q >> (2 * CGb);
    int nx = qx + cNX[k], ny = qy + cNY[k], nz = qz + cNZ[k];
    int c = 0;
    if ((unsigned)nx < (unsigned)CG && (unsigned)ny < (unsigned)CG && (unsigned)nz < (unsigned)CG) {
        int fa = (2 * qx + (a & 1)) + ((2 * qy + ((a >> 1) & 1)) << FLb) + ((2 * qz + (a >> 2)) << (2 * FLb));
        if (__ldg(rinfo + fa)) {
            int m = g.bmask[(k << 3) | a];
            int bb = 2 * nx + (2 * ny << FLb) + (2 * nz << (2 * FLb));
            const int2* rp = (const int2*)rinfo;
            int2 r01 = __ldg(rp + (bb >> 1));
            int2 r23 = __ldg(rp + ((bb + FL) >> 1));
            int2 r45 = __ldg(rp + ((bb + FLsq) >> 1));
            int2 r67 = __ldg(rp + ((bb + FLsq + FL) >> 1));
            c  = ((m >> 0) & 1) & (r01.x != 0);
            c += ((m >> 1) & 1) & (r01.y != 0);
            c += ((m >> 2) & 1) & (r23.x != 0);
            c += ((m >> 3) & 1) & (r23.y != 0);
            c += ((m >> 4) & 1) & (r45.x != 0);
            c += ((m >> 5) & 1) & (r45.y != 0);
            c += ((m >> 6) & 1) & (r67.x != 0);
            c += ((m >> 7) & 1) & (r67.y != 0);
        }
    }
    ecnt[idx] = c;
}

__global__ void k_ewriteAll(const int* __restrict__ eoff, float* __restrict__ out) {
    int idx = blockIdx.x * 256 + threadIdx.x;
    if (idx >= 8088768) return;
    int local, CGb; const int* rinfo;
    edgeDecode(idx, local, CGb, rinfo);
    int CG = 1 << CGb, FLb = CGb + 1, FL = 1 << FLb, FLsq = 1 << (2 * FLb);
    int a = local & 7, qk = local >> 3;
    int k = qk % 27, q = qk / 27;
    int qx = q & (CG - 1), qy = (q >> CGb) & (CG - 1), qz = q >> (2 * CGb);
    int nx = qx + cNX[k], ny = qy + cNY[k], nz = qz + cNZ[k];
    if (!((unsigned)nx < (unsigned)CG && (unsigned)ny < (unsigned)CG && (unsigned)nz < (unsigned)CG))
        return;
    int fa = (2 * qx + (a & 1)) + ((2 * qy + ((a >> 1) & 1)) << FLb) + ((2 * qz + (a >> 2)) << (2 * FLb));
    int ra1 = __ldg(rinfo + fa);
    if (!ra1) return;
    float ra = (float)(ra1 - 1);
    int m = g.bmask[(k << 3) | a];
    int bb = 2 * nx + (2 * ny << FLb) + (2 * nz << (2 * FLb));
    const int2* rp = (const int2*)rinfo;
    int2 r01 = __ldg(rp + (bb >> 1));
    int2 r23 = __ldg(rp + ((bb + FL) >> 1));
    int2 r45 = __ldg(rp + ((bb + FLsq) >> 1));
    int2 r67 = __ldg(rp + ((bb + FLsq + FL) >> 1));
    int rv[8] = {r01.x, r01.y, r23.x, r23.y, r45.x, r45.y, r67.x, r67.y};
    int E = g.E;
    float* o0 = out + g.oedge + __ldg(eoff + idx);
#pragma unroll
    for (int b = 0; b < 8; b++) {
        if (((m >> b) & 1) && rv[b]) {
            o0[0] = (float)(rv[b] - 1);
            o0[E] = ra;
            o0++;
        }
    }
}

// ------------------------------------------------------------------ sv
__global__ void k_sv0(const float* __restrict__ nodes) {
    int i = blockIdx.x * blockDim.x + threadIdx.x;
    if (i >= NPT) return;
    int s = g.seg0[i];
    float m = nodes[i * 10];
    float* row = g.svraw + (size_t)s * 10;
    atomicAdd(row, m);
#pragma unroll
    for (int j = 1; j < 10; j++)
        atomicAdd(row + j, m * nodes[i * 10 + j]);
}

__global__ void k_svagg(int soffP, int soffC, const int* __restrict__ seg, int npIdx) {
    int r = blockIdx.x * blockDim.x + threadIdx.x;
    if (r >= g.tot[npIdx]) return;
    const float* pr = g.svraw + (size_t)(soffP + r) * 10;
    float* row = g.svraw + (size_t)(soffC + seg[r]) * 10;
#pragma unroll
    for (int j = 0; j < 10; j++)
        atomicAdd(row + j, pr[j]);
}

// ------------------------------------------------------------------ layout + writers
__global__ void k_off() {
    int n0 = g.tot[0], n1 = g.tot[1], n2 = g.tot[2], n3 = g.tot[3], n4 = g.tot[4];
    int T = g.tot[5], E = g.tot[6];
    int A = NPT + n0 + n1 + n2 + n3;
    int S = n0 + n1 + n2 + n3 + n4;
    g.A = A; g.S = S; g.E = E;
    g.oassign = 2 * T;
    g.osv = 2 * T + 2 * A;
    g.oedge = g.osv + 10 * S;
    g.oids = g.oedge + 2 * E;
    g.svb[0] = 0; g.svb[1] = n0; g.svb[2] = n0 + n1; g.svb[3] = n0 + n1 + n2; g.svb[4] = n0 + n1 + n2 + n3;
    g.ab[0] = 0; g.ab[1] = NPT; g.ab[2] = NPT + n0; g.ab[3] = NPT + n0 + n1; g.ab[4] = NPT + n0 + n1 + n2;
}

__global__ void k_awriteAll(float* __restrict__ out) {
    int t = blockIdx.x * blockDim.x + threadIdx.x;
    if (t >= g.A) return;
    const int* ord; const int* seg; int loc;
    if (t < g.ab[1])      { ord = g.order0;          seg = g.seg0;            loc = t; }
    else if (t < g.ab[2]) { ord = g.ordL + 0;        seg = g.segL + 0;        loc = t - g.ab[1]; }
    else if (t < g.ab[3]) { ord = g.ordL + 262144;   seg = g.segL + 262144;   loc = t - g.ab[2]; }
    else if (t < g.ab[4]) { ord = g.ordL + 294912;   seg = g.segL + 294912;   loc = t - g.ab[3]; }
    else                  { ord = g.ordL + 299008;   seg = g.segL + 299008;   loc = t - g.ab[4]; }
    int p = ord[loc];
    out[g.oassign + t] = (float)seg[p];
    out[g.oassign + g.A + t] = (float)p;
}

__global__ void k_svidwrite(float* __restrict__ out) {
    int r = blockIdx.x * blockDim.x + threadIdx.x;
    if (r >= g.S) return;
    int neo;
    if (r < g.svb[1])      neo = 0;
    else if (r < g.svb[2]) neo = 262144 - g.svb[1];
    else if (r < g.svb[3]) neo = 294912 - g.svb[2];
    else if (r < g.svb[4]) neo = 299008 - g.svb[3];
    else                   neo = 299520 - g.svb[4];
    int loc = neo + r;
    out[g.oids + r] = (float)g.neA[loc];
    const float* raw = g.svraw + (size_t)loc * 10;
    float m = raw[0];
    float* o = out + g.osv + (size_t)r * 10;
    o[0] = m;
#pragma unroll
    for (int j = 1; j < 10; j++) o[j] = raw[j] / m;
}

// ------------------------------------------------------------------ host
extern "C" void kernel_launch(void* const* d_in, const int* in_sizes, int n_in,
                              void* d_out, int out_size) {
    const float* nodes = (const float*)d_in[0];
    float* out = (float*)d_out;
    GG* G;
    cudaGetSymbolAddress((void**)&G, g);
    int *rinfoL, *ecnt8, *eoff8;
    cudaGetSymbolAddress((void**)&rinfoL, g_rinfoL);
    cudaGetSymbolAddress((void**)&ecnt8, g_ecnt8);
    cudaGetSymbolAddress((void**)&eoff8, g_eoff8);

    cudaMemsetAsync(G, 0, offsetof(GG, zend), 0);
    k_init2<<<1, 256>>>();
    k_foldpre<<<768, 256>>>(nodes);
    k_mmx<<<16, 256>>>(nodes);
    k_fold3b<<<1, 128>>>(nodes);
    k_cells<<<NPT / 256, 256>>>(nodes);
    k_scan2<<<32, 512>>>(G->occ0, G->cnt0, G->rank0, G->cstart0, C0, &G->tot[0], 0, 0);
    k_post0<<<C0 / 256, 256>>>();
    k_scatseg<<<NPT / 256, 256>>>();
    k_sort0<<<C0 / 256, 256>>>();
    k_scan1<<<32, 512>>>(G->pdeg, G->poff, NPT, &G->tot[5], 1, 32);

    // level 1
    k_l1occup<<<NPT / 256, 256>>>();
    k_scan1<<<4, 512>>>(G->occL, G->rankL, 32768, &G->tot[1], 2, 64);
    k_l1post<<<32768 / 256, 256>>>();
    k_l1seg<<<NPT / 256, 256>>>();
    k_scan1<<<4, 512>>>(G->cntL, G->cstartL, 32768, nullptr, 3, 68);
    k_l1scat<<<NPT / 256, 256>>>();
    k_l1sort<<<32768 / 256, 256>>>();

    // levels 2..4 (single-block megakernels)
    k_mega<16, 5><<<1, 1024>>>(G->neA + 262144, 1, 2, rinfoL + 32768, G->neA + 294912,
                               G->segL + 262144, G->ordL + 262144);
    k_mega<8, 4><<<1, 1024>>>(G->neA + 294912, 2, 3, rinfoL + 36864, G->neA + 299008,
                              G->segL + 294912, G->ordL + 294912);
    k_mega<4, 3><<<1, 1024>>>(G->neA + 299008, 3, 4, rinfoL + 37376, G->neA + 299520,
                              G->segL + 299008, G->ordL + 299008);

    // edges: one count kernel + one scan + one writer
    k_ecntAll<<<(8088768 + 255) / 256, 256>>>(ecnt8);
    k_scan1<<<(8088768 + 8191) / 8192, 512>>>(ecnt8, eoff8, 8088768, &G->tot[6], 4, 72);

    k_off<<<1, 1>>>();

    // supervoxel features (raw sums; normalize at output)
    k_sv0<<<NPT / 256, 256>>>(nodes);
    k_svagg<<<NPT / 256, 256>>>(0, 262144, G->segL + 0, 0);
    k_svagg<<<(262144 + 255) / 256, 256>>>(262144, 294912, G->segL + 262144, 1);
    k_svagg<<<(32768 + 255) / 256, 256>>>(294912, 299008, G->segL + 294912, 2);
    k_svagg<<<(4096 + 255) / 256, 256>>>(299008, 299520, G->segL + 299008, 3);

    // writers
    k_gwrite<<<NPT / 256, 256>>>(out);
    k_awriteAll<<<(NPT + 299520 + 255) / 256, 256>>>(out);
    k_svidwrite<<<(299584 + 255) / 256, 256>>>(out);
    k_ewriteAll<<<(8088768 + 255) / 256, 256>>>(eoff8, out);
    (void)in_sizes; (void)n_in; (void)out_size;
}